// round 9
// baseline (speedup 1.0000x reference)
#include <cuda_runtime.h>
#include <cstdint>

#define FULLMASK 0xffffffffu
typedef unsigned long long ull;
namespace {
constexpr int B_ = 16, N_ = 4096, S_ = 1024, K_ = 32;
constexpr float EPSF = 1e-5f;
constexpr int FPS_SMEM = 3 * N_ * 4;
constexpr int KNN_SMEM = 4 * N_ * 4;
constexpr int L0_SMEM = (68 * 256 + 67 * 64 + 2 * 32 * 65) * 4;    // 103424
constexpr int L1_SMEM = (64 * 256 + 64 * 64 + 2 * 32 * 65) * 4;    // 98560
constexpr int L2_SMEM = (64 * 256 + 64 * 128 + 2 * 32 * 129) * 4;  // 131328
}

// ------------- scratch -------------
__device__ int      g_fps[B_ * S_];
__device__ float    g_newxyz[B_ * S_ * 3];
__device__ float    g_d2[B_ * N_];
__device__ int      g_nn[B_ * S_ * K_];
__device__ float    g_y0[B_ * S_ * K_ * 64];
__device__ float    g_y1[B_ * S_ * K_ * 64];
__device__ float    g_pmax[B_ * S_ * 128];
__device__ float    g_pmin[B_ * S_ * 128];
__device__ float    g_part0[2048 * 128];
__device__ float    g_part1[2048 * 128];
__device__ float    g_part2[2048 * 256];
__device__ float    g_scale0[64], g_shift0[64];
__device__ float    g_scale1[64], g_shift1[64];
__device__ float    g_scale2[128], g_shift2[128];

// ------------- packed fp32x2 helpers (bit-exact: independent IEEE rn lanes) ----
__device__ __forceinline__ ull pack2(float lo, float hi) {
    ull r;
    asm("mov.b64 %0, {%1, %2};" : "=l"(r) : "f"(lo), "f"(hi));
    return r;
}
__device__ __forceinline__ void fma2(ull& d, ull a, ull b) {
    asm("fma.rn.f32x2 %0, %1, %2, %0;" : "+l"(d) : "l"(a), "l"(b));
}
__device__ __forceinline__ ull add2(ull a, ull b) {
    ull r; asm("add.rn.f32x2 %0, %1, %2;" : "=l"(r) : "l"(a), "l"(b)); return r;
}
__device__ __forceinline__ ull mul2(ull a, ull b) {
    ull r; asm("mul.rn.f32x2 %0, %1, %2;" : "=l"(r) : "l"(a), "l"(b)); return r;
}
__device__ __forceinline__ float2 unpack2(ull v) {
    float lo, hi;
    asm("mov.b64 {%0, %1}, %2;" : "=f"(lo), "=f"(hi) : "l"(v));
    return make_float2(lo, hi);
}

// ------------- KNN helpers -------------
__device__ __forceinline__ void cmpswap(float& k, int& v, int j, bool dirAsc, int lane) {
    float ok = __shfl_xor_sync(FULLMASK, k, j);
    int   ov = __shfl_xor_sync(FULLMASK, v, j);
    bool takeOther = (((lane & j) == 0) == dirAsc) ? (ok < k) : (ok > k);
    if (takeOther) { k = ok; v = ov; }
}
__device__ __forceinline__ void bitonic_merge_asc(float& k, int& v, int lane) {
    #pragma unroll
    for (int j = 16; j > 0; j >>= 1) cmpswap(k, v, j, true, lane);
}
__device__ __forceinline__ void bitonic_sort_asc(float& k, int& v, int lane) {
    #pragma unroll
    for (int kk = 2; kk <= 16; kk <<= 1) {
        bool dir = ((lane & kk) == 0);
        #pragma unroll
        for (int j = kk >> 1; j > 0; j >>= 1) cmpswap(k, v, j, dir, lane);
    }
    bitonic_merge_asc(k, v, lane);
}

// ------------- FPS: one CTA per batch, packed f32x2 distance math -------------
__global__ void __launch_bounds__(1024) fps_kernel(const float* __restrict__ xyz) {
    int b = blockIdx.x;
    extern __shared__ float sh[];
    float* sx = sh; float* sy = sh + N_; float* sz = sh + 2 * N_;
    __shared__ unsigned swv[2][32];
    __shared__ unsigned swi[2][32];
    int t = threadIdx.x, w = t >> 5, lane = t & 31;
    const float* X = xyz + (size_t)b * N_ * 3;
    for (int i = t; i < N_; i += 1024) { sx[i] = X[3*i]; sy[i] = X[3*i+1]; sz[i] = X[3*i+2]; }
    __syncthreads();
    ull rxp[2], ryp[2], rzp[2];
    float dist[4];
    #pragma unroll
    for (int p = 0; p < 2; p++) {
        int i0 = t + (2*p) * 1024, i1 = t + (2*p+1) * 1024;
        rxp[p] = pack2(sx[i0], sx[i1]);
        ryp[p] = pack2(sy[i0], sy[i1]);
        rzp[p] = pack2(sz[i0], sz[i1]);
        dist[2*p] = 1e10f; dist[2*p+1] = 1e10f;
    }
    int far = 0;
    for (int it = 0; it < S_; ++it) {
        if (t == 0) g_fps[b * S_ + it] = far;
        float cx = sx[far], cy = sy[far], cz = sz[far];
        ull ncx = pack2(-cx, -cx), ncy = pack2(-cy, -cy), ncz = pack2(-cz, -cz);
        float bv = -1.0f; int bi = 0;
        #pragma unroll
        for (int p = 0; p < 2; p++) {
            ull dx = add2(rxp[p], ncx);
            ull dy = add2(ryp[p], ncy);
            ull dz = add2(rzp[p], ncz);
            ull s = add2(add2(mul2(dx,dx), mul2(dy,dy)), mul2(dz,dz));
            float2 d = unpack2(s);
            float dm0 = fminf(dist[2*p], d.x);   dist[2*p] = dm0;
            if (dm0 > bv) { bv = dm0; bi = t + (2*p) * 1024; }
            float dm1 = fminf(dist[2*p+1], d.y); dist[2*p+1] = dm1;
            if (dm1 > bv) { bv = dm1; bi = t + (2*p+1) * 1024; }
        }
        unsigned db = __float_as_uint(bv);
        unsigned mx = __reduce_max_sync(FULLMASK, db);
        unsigned cand = (db == mx) ? (unsigned)bi : 0xffffffffu;
        unsigned mi = __reduce_min_sync(FULLMASK, cand);
        int buf = it & 1;
        if (lane == 0) { swv[buf][w] = mx; swi[buf][w] = mi; }
        __syncthreads();
        unsigned v2 = swv[buf][lane];
        unsigned i2 = swi[buf][lane];
        unsigned mx2 = __reduce_max_sync(FULLMASK, v2);
        unsigned c2 = (v2 == mx2) ? i2 : 0xffffffffu;
        far = (int)__reduce_min_sync(FULLMASK, c2);
    }
}

// ------------- prep: ||x||^2 + gather new_xyz -------------
__global__ void prep_kernel(const float* __restrict__ xyz, float* __restrict__ out, int write_xyz) {
    int i = blockIdx.x * 256 + threadIdx.x;
    if (i < B_ * N_) {
        float x = xyz[3*i], y = xyz[3*i+1], z = xyz[3*i+2];
        g_d2[i] = __fadd_rn(__fadd_rn(__fmul_rn(x,x), __fmul_rn(y,y)), __fmul_rn(z,z));
    }
    if (i < B_ * S_) {
        int b = i >> 10, n = g_fps[i];
        const float* p = xyz + ((size_t)b * N_ + n) * 3;
        float px = p[0], py = p[1], pz = p[2];
        g_newxyz[3*i] = px; g_newxyz[3*i+1] = py; g_newxyz[3*i+2] = pz;
        if (write_xyz) { out[3*i] = px; out[3*i+1] = py; out[3*i+2] = pz; }
    }
}

// ------------- KNN: warp per query, bitonic top-32, exact fp32 -------------
__global__ void __launch_bounds__(256) knn_kernel(const float* __restrict__ xyz) {
    extern __shared__ float sh[];
    float* sx = sh; float* sy = sh + N_; float* sz = sh + 2*N_; float* sd = sh + 3*N_;
    int t = threadIdx.x;
    int b = blockIdx.x >> 7;
    int s0 = (blockIdx.x & 127) * 8;
    const float* X = xyz + (size_t)b * N_ * 3;
    for (int i = t; i < N_; i += 256) {
        sx[i] = X[3*i]; sy[i] = X[3*i+1]; sz[i] = X[3*i+2];
        sd[i] = g_d2[b * N_ + i];
    }
    __syncthreads();
    int w = t >> 5, lane = t & 31;
    int q = b * S_ + s0 + w;
    float qx = g_newxyz[3*q], qy = g_newxyz[3*q+1], qz = g_newxyz[3*q+2];
    float q2 = __fadd_rn(__fadd_rn(__fmul_rn(qx,qx), __fmul_rn(qy,qy)), __fmul_rn(qz,qz));
    float key = 3.0e38f; int kid = 0; float curmax = 3.0e38f;
    for (int c = 0; c < N_ / 32; c++) {
        int p = c * 32 + lane;
        float dot = __fadd_rn(__fadd_rn(__fmul_rn(qx, sx[p]),
                                        __fmul_rn(qy, sy[p])),
                              __fmul_rn(qz, sz[p]));
        float d = __fsub_rn(__fadd_rn(q2, sd[p]), __fmul_rn(2.0f, dot));
        if (!__ballot_sync(FULLMASK, d < curmax)) continue;
        float nk = d; int ni = p;
        bitonic_sort_asc(nk, ni, lane);
        float rk = __shfl_sync(FULLMASK, nk, 31 - lane);
        int   ri = __shfl_sync(FULLMASK, ni, 31 - lane);
        if (rk < key) { key = rk; kid = ri; }
        bitonic_merge_asc(key, kid, lane);
        curmax = __shfl_sync(FULLMASK, key, 31);
    }
    g_nn[q * K_ + lane] = kid;
}

// ================= layer GEMMs: block = 256 rows, thread = 8 rows x 8 cols ====

// ------------- layer 0: gather + GEMM 67->64 -------------
__global__ void __launch_bounds__(256, 2) layer0_kernel(const float* __restrict__ xyz,
                                                        const float* __restrict__ points,
                                                        const float* __restrict__ w,
                                                        const float* __restrict__ bias) {
    extern __shared__ float sh[];
    float* XsT = sh;                   // [68][256]
    float* Ws  = XsT + 68 * 256;       // [67][64]
    float* Red = Ws + 67 * 64;         // 2 x [32][65]
    int t = threadIdx.x;
    for (int idx = t; idx < 67 * 64; idx += 256) {
        int cc = idx >> 6, o = idx & 63;
        int c = (cc < 64) ? (cc + 3) : (cc - 64);
        Ws[idx] = w[o * 67 + c];
    }
    {
        int r = t;
        int gr = blockIdx.x * 256 + r;
        int q = gr >> 5, b = gr >> 15;
        int n = g_nn[gr];
        const float4* prow = (const float4*)(points + ((size_t)b * N_ + n) * 64);
        #pragma unroll 4
        for (int ch = 0; ch < 16; ch++) {
            float4 v = prow[ch];
            XsT[(ch*4+0)*256 + r] = v.x;
            XsT[(ch*4+1)*256 + r] = v.y;
            XsT[(ch*4+2)*256 + r] = v.z;
            XsT[(ch*4+3)*256 + r] = v.w;
        }
        const float* pp = xyz + ((size_t)b * N_ + n) * 3;
        XsT[64*256 + r] = __fadd_rn(pp[0], -g_newxyz[3*q]);
        XsT[65*256 + r] = __fadd_rn(pp[1], -g_newxyz[3*q+1]);
        XsT[66*256 + r] = __fadd_rn(pp[2], -g_newxyz[3*q+2]);
    }
    __syncthreads();
    int rg = t >> 3, cg = t & 7;       // rows rg*8..+7, cols cg*8..+7
    ull acc[4][8];                     // [row-pair][col]
    #pragma unroll
    for (int i = 0; i < 8; i++) {
        float bb = bias[cg*8+i];
        ull bp = pack2(bb, bb);
        #pragma unroll
        for (int p = 0; p < 4; p++) acc[p][i] = bp;
    }
    for (int c = 0; c < 67; c++) {
        const float4* ap = (const float4*)(XsT + c*256 + rg*8);
        float4 a0 = ap[0], a1 = ap[1];
        ull apair[4] = {pack2(a0.x,a0.y), pack2(a0.z,a0.w),
                        pack2(a1.x,a1.y), pack2(a1.z,a1.w)};
        const float4* wp = (const float4*)(Ws + c*64 + cg*8);
        float4 w0 = wp[0], w1 = wp[1];
        float wf[8] = {w0.x,w0.y,w0.z,w0.w,w1.x,w1.y,w1.z,w1.w};
        #pragma unroll
        for (int i = 0; i < 8; i++) {
            ull wd = pack2(wf[i], wf[i]);
            #pragma unroll
            for (int p = 0; p < 4; p++) fma2(acc[p][i], apair[p], wd);
        }
    }
    float s1[8], s2[8];
    #pragma unroll
    for (int i = 0; i < 8; i++) { s1[i] = 0.f; s2[i] = 0.f; }
    #pragma unroll
    for (int p = 0; p < 4; p++) {
        float lo[8], hi[8];
        #pragma unroll
        for (int i = 0; i < 8; i++) { float2 v = unpack2(acc[p][i]); lo[i] = v.x; hi[i] = v.y; }
        size_t r0 = (size_t)blockIdx.x * 256 + rg*8 + 2*p;
        float4* d0 = (float4*)(g_y0 + r0 * 64 + cg*8);
        d0[0] = make_float4(lo[0],lo[1],lo[2],lo[3]);
        d0[1] = make_float4(lo[4],lo[5],lo[6],lo[7]);
        float4* d1 = (float4*)(g_y0 + (r0+1) * 64 + cg*8);
        d1[0] = make_float4(hi[0],hi[1],hi[2],hi[3]);
        d1[1] = make_float4(hi[4],hi[5],hi[6],hi[7]);
        #pragma unroll
        for (int i = 0; i < 8; i++) { s1[i] += lo[i]+hi[i]; s2[i] += lo[i]*lo[i]+hi[i]*hi[i]; }
    }
    #pragma unroll
    for (int i = 0; i < 8; i++) {
        int col = cg*8 + i;
        Red[rg*65 + col]        = s1[i];
        Red[2080 + rg*65 + col] = s2[i];
    }
    __syncthreads();
    if (t < 64) {
        float s = 0.f;
        #pragma unroll 8
        for (int j = 0; j < 32; j++) s += Red[j*65 + t];
        g_part0[blockIdx.x*128 + t] = s;
    } else if (t < 128) {
        int col = t - 64; float s = 0.f;
        #pragma unroll 8
        for (int j = 0; j < 32; j++) s += Red[2080 + j*65 + col];
        g_part0[blockIdx.x*128 + 64 + col] = s;
    }
}

// ------------- layer 1: BN0+ReLU fused gather, GEMM 64->64 -------------
__global__ void __launch_bounds__(256, 2) layer1_kernel(const float* __restrict__ w,
                                                        const float* __restrict__ bias) {
    extern __shared__ float sh[];
    float* XsT = sh;                   // [64][256]
    float* Ws  = XsT + 64 * 256;       // [64][64]
    float* Red = Ws + 64 * 64;         // 2 x [32][65]
    __shared__ float sS[64], sH[64];
    int t = threadIdx.x;
    if (t < 64) { sS[t] = g_scale0[t]; sH[t] = g_shift0[t]; }
    for (int idx = t; idx < 64 * 64; idx += 256) {
        int c = idx >> 6, o = idx & 63;
        Ws[idx] = w[o * 64 + c];
    }
    __syncthreads();
    {
        int r = t;
        size_t gr = (size_t)blockIdx.x * 256 + r;
        const float4* src = (const float4*)(g_y0 + gr * 64);
        #pragma unroll 4
        for (int ch = 0; ch < 16; ch++) {
            float4 v = src[ch]; int c0 = ch * 4;
            XsT[(c0+0)*256 + r] = fmaxf(0.f, fmaf(v.x, sS[c0],   sH[c0]));
            XsT[(c0+1)*256 + r] = fmaxf(0.f, fmaf(v.y, sS[c0+1], sH[c0+1]));
            XsT[(c0+2)*256 + r] = fmaxf(0.f, fmaf(v.z, sS[c0+2], sH[c0+2]));
            XsT[(c0+3)*256 + r] = fmaxf(0.f, fmaf(v.w, sS[c0+3], sH[c0+3]));
        }
    }
    __syncthreads();
    int rg = t >> 3, cg = t & 7;
    ull acc[4][8];
    #pragma unroll
    for (int i = 0; i < 8; i++) {
        float bb = bias[cg*8+i];
        ull bp = pack2(bb, bb);
        #pragma unroll
        for (int p = 0; p < 4; p++) acc[p][i] = bp;
    }
    for (int c = 0; c < 64; c++) {
        const float4* ap = (const float4*)(XsT + c*256 + rg*8);
        float4 a0 = ap[0], a1 = ap[1];
        ull apair[4] = {pack2(a0.x,a0.y), pack2(a0.z,a0.w),
                        pack2(a1.x,a1.y), pack2(a1.z,a1.w)};
        const float4* wp = (const float4*)(Ws + c*64 + cg*8);
        float4 w0 = wp[0], w1 = wp[1];
        float wf[8] = {w0.x,w0.y,w0.z,w0.w,w1.x,w1.y,w1.z,w1.w};
        #pragma unroll
        for (int i = 0; i < 8; i++) {
            ull wd = pack2(wf[i], wf[i]);
            #pragma unroll
            for (int p = 0; p < 4; p++) fma2(acc[p][i], apair[p], wd);
        }
    }
    float s1[8], s2[8];
    #pragma unroll
    for (int i = 0; i < 8; i++) { s1[i] = 0.f; s2[i] = 0.f; }
    #pragma unroll
    for (int p = 0; p < 4; p++) {
        float lo[8], hi[8];
        #pragma unroll
        for (int i = 0; i < 8; i++) { float2 v = unpack2(acc[p][i]); lo[i] = v.x; hi[i] = v.y; }
        size_t r0 = (size_t)blockIdx.x * 256 + rg*8 + 2*p;
        float4* d0 = (float4*)(g_y1 + r0 * 64 + cg*8);
        d0[0] = make_float4(lo[0],lo[1],lo[2],lo[3]);
        d0[1] = make_float4(lo[4],lo[5],lo[6],lo[7]);
        float4* d1 = (float4*)(g_y1 + (r0+1) * 64 + cg*8);
        d1[0] = make_float4(hi[0],hi[1],hi[2],hi[3]);
        d1[1] = make_float4(hi[4],hi[5],hi[6],hi[7]);
        #pragma unroll
        for (int i = 0; i < 8; i++) { s1[i] += lo[i]+hi[i]; s2[i] += lo[i]*lo[i]+hi[i]*hi[i]; }
    }
    #pragma unroll
    for (int i = 0; i < 8; i++) {
        int col = cg*8 + i;
        Red[rg*65 + col]        = s1[i];
        Red[2080 + rg*65 + col] = s2[i];
    }
    __syncthreads();
    if (t < 64) {
        float s = 0.f;
        #pragma unroll 8
        for (int j = 0; j < 32; j++) s += Red[j*65 + t];
        g_part1[blockIdx.x*128 + t] = s;
    } else if (t < 128) {
        int col = t - 64; float s = 0.f;
        #pragma unroll 8
        for (int j = 0; j < 32; j++) s += Red[2080 + j*65 + col];
        g_part1[blockIdx.x*128 + 64 + col] = s;
    }
}

// ------------- layer 2 fused: BN1+ReLU gather, GEMM 64->128, max/min over K ----
__global__ void __launch_bounds__(512, 1) layer2_kernel(const float* __restrict__ w,
                                                        const float* __restrict__ bias) {
    extern __shared__ float sh[];
    float* XsT = sh;                   // [64][256]
    float* Ws  = XsT + 64 * 256;       // [64][128]
    float* Red = Ws + 64 * 128;        // 2 x [32][129]
    __shared__ float sS[64], sH[64];
    int t = threadIdx.x;
    if (t < 64) { sS[t] = g_scale1[t]; sH[t] = g_shift1[t]; }
    for (int idx = t; idx < 64 * 128; idx += 512) {
        int c = idx >> 7, o = idx & 127;
        Ws[idx] = w[o * 64 + c];
    }
    __syncthreads();
    {
        int r = t & 255, half = t >> 8;
        size_t gr = (size_t)blockIdx.x * 256 + r;
        const float4* src = (const float4*)(g_y1 + gr * 64);
        for (int ch = half; ch < 16; ch += 2) {
            float4 v = src[ch]; int c0 = ch * 4;
            XsT[(c0+0)*256 + r] = fmaxf(0.f, fmaf(v.x, sS[c0],   sH[c0]));
            XsT[(c0+1)*256 + r] = fmaxf(0.f, fmaf(v.y, sS[c0+1], sH[c0+1]));
            XsT[(c0+2)*256 + r] = fmaxf(0.f, fmaf(v.z, sS[c0+2], sH[c0+2]));
            XsT[(c0+3)*256 + r] = fmaxf(0.f, fmaf(v.w, sS[c0+3], sH[c0+3]));
        }
    }
    __syncthreads();
    int rg = t >> 4, cg = t & 15;      // rows rg*8..+7 (256), cols cg*8..+7 (128)
    ull acc[4][8];
    #pragma unroll
    for (int i = 0; i < 8; i++) {
        float bb = bias[cg*8+i];
        ull bp = pack2(bb, bb);
        #pragma unroll
        for (int p = 0; p < 4; p++) acc[p][i] = bp;
    }
    for (int c = 0; c < 64; c++) {
        const float4* ap = (const float4*)(XsT + c*256 + rg*8);
        float4 a0 = ap[0], a1 = ap[1];
        ull apair[4] = {pack2(a0.x,a0.y), pack2(a0.z,a0.w),
                        pack2(a1.x,a1.y), pack2(a1.z,a1.w)};
        const float4* wp = (const float4*)(Ws + c*128 + cg*8);
        float4 w0 = wp[0], w1 = wp[1];
        float wf[8] = {w0.x,w0.y,w0.z,w0.w,w1.x,w1.y,w1.z,w1.w};
        #pragma unroll
        for (int i = 0; i < 8; i++) {
            ull wd = pack2(wf[i], wf[i]);
            #pragma unroll
            for (int p = 0; p < 4; p++) fma2(acc[p][i], apair[p], wd);
        }
    }
    // stats + max/min over this thread's 8 rows (all within (b,s) group rg>>2)
    float s1[8], s2[8], mx[8], mn[8];
    #pragma unroll
    for (int i = 0; i < 8; i++) { s1[i]=0.f; s2[i]=0.f; mx[i]=-3.4e38f; mn[i]=3.4e38f; }
    #pragma unroll
    for (int p = 0; p < 4; p++) {
        #pragma unroll
        for (int i = 0; i < 8; i++) {
            float2 v = unpack2(acc[p][i]);
            s1[i] += v.x + v.y;
            s2[i] += v.x*v.x + v.y*v.y;
            mx[i] = fmaxf(mx[i], fmaxf(v.x, v.y));
            mn[i] = fminf(mn[i], fminf(v.x, v.y));
        }
    }
    #pragma unroll
    for (int i = 0; i < 8; i++) {
        int col = cg*8 + i;
        Red[rg*129 + col]        = s1[i];
        Red[4128 + rg*129 + col] = s2[i];
    }
    __syncthreads();
    if (t < 128) {
        float s = 0.f;
        #pragma unroll 8
        for (int j = 0; j < 32; j++) s += Red[j*129 + t];
        g_part2[blockIdx.x*256 + t] = s;
    } else if (t < 256) {
        int col = t - 128; float s = 0.f;
        #pragma unroll 8
        for (int j = 0; j < 32; j++) s += Red[4128 + j*129 + col];
        g_part2[blockIdx.x*256 + 128 + col] = s;
    }
    __syncthreads();
    #pragma unroll
    for (int i = 0; i < 8; i++) {
        int col = cg*8 + i;
        Red[rg*129 + col]        = mx[i];
        Red[4128 + rg*129 + col] = mn[i];
    }
    __syncthreads();
    {
        // 8 (b,s) groups of 32 rows: group g = rg 4g..4g+3
        int col = t & 127, sel = t >> 7;   // sel: 0=max g0-3, 1=min g0-3, 2=max g4-7, 3=min g4-7
        int gbase = (sel >> 1) * 4;
        bool domax = (sel & 1) == 0;
        #pragma unroll
        for (int gi = 0; gi < 4; gi++) {
            int g = gbase + gi;
            size_t bs = (size_t)blockIdx.x * 8 + g;
            if (domax) {
                float m = -3.4e38f;
                #pragma unroll
                for (int j = 0; j < 4; j++) m = fmaxf(m, Red[(4*g+j)*129 + col]);
                g_pmax[bs*128 + col] = m;
            } else {
                float n = 3.4e38f;
                #pragma unroll
                for (int j = 0; j < 4; j++) n = fminf(n, Red[4128 + (4*g+j)*129 + col]);
                g_pmin[bs*128 + col] = n;
            }
        }
    }
}

// ------------- BN stats -------------
__global__ void __launch_bounds__(256) stats_kernel(int layer, int nblk, int C,
                             const float* __restrict__ gamma, const float* __restrict__ beta) {
    int c = blockIdx.x;
    int t = threadIdx.x;
    const float* part = (layer == 0) ? g_part0 : (layer == 1) ? g_part1 : g_part2;
    float s1 = 0.f, s2 = 0.f;
    for (int bk = t; bk < nblk; bk += 256) {
        s1 += part[(size_t)bk*2*C + c];
        s2 += part[(size_t)bk*2*C + C + c];
    }
    __shared__ float r1[256], r2[256];
    r1[t] = s1; r2[t] = s2;
    __syncthreads();
    for (int off = 128; off >= 1; off >>= 1) {
        if (t < off) { r1[t] += r1[t+off]; r2[t] += r2[t+off]; }
        __syncthreads();
    }
    if (t == 0) {
        const float n = 524288.f;
        float mean = r1[0] / n;
        float var = r2[0] / n - mean * mean;
        float sc = gamma[c] * rsqrtf(var + EPSF);
        float sf = beta[c] - mean * sc;
        if (layer == 0)      { g_scale0[c] = sc; g_shift0[c] = sf; }
        else if (layer == 1) { g_scale1[c] = sc; g_shift1[c] = sf; }
        else                 { g_scale2[c] = sc; g_shift2[c] = sf; }
    }
}

// ------------- pool epilogue -------------
__global__ void pool2_kernel(float* __restrict__ out, int pts_off) {
    int bs = blockIdx.x;
    int c = threadIdx.x;
    float sc = g_scale2[c], sf = g_shift2[c];
    float v = (sc >= 0.f) ? g_pmax[(size_t)bs*128 + c] : g_pmin[(size_t)bs*128 + c];
    float m = fmaxf(fmaf(v, sc, sf), 0.f);
    out[pts_off + (bs >> 10) * (128 * 1024) + c * 1024 + (bs & 1023)] = m;
}

extern "C" void kernel_launch(void* const* d_in, const int* in_sizes, int n_in,
                              void* d_out, int out_size) {
    const float* xyz    = (const float*)d_in[0];
    const float* points = (const float*)d_in[1];
    const float* w0 = (const float*)d_in[2];  const float* b0  = (const float*)d_in[3];
    const float* g0 = (const float*)d_in[4];  const float* be0 = (const float*)d_in[5];
    const float* w1 = (const float*)d_in[6];  const float* b1  = (const float*)d_in[7];
    const float* g1 = (const float*)d_in[8];  const float* be1 = (const float*)d_in[9];
    const float* w2 = (const float*)d_in[10]; const float* b2  = (const float*)d_in[11];
    const float* g2 = (const float*)d_in[12]; const float* be2 = (const float*)d_in[13];
    float* out = (float*)d_out;

    int npts = B_ * 128 * S_;
    int pts_off = out_size - npts;
    if (pts_off < 0) pts_off = 0;

    cudaFuncSetAttribute(fps_kernel,    cudaFuncAttributeMaxDynamicSharedMemorySize, FPS_SMEM);
    cudaFuncSetAttribute(knn_kernel,    cudaFuncAttributeMaxDynamicSharedMemorySize, KNN_SMEM);
    cudaFuncSetAttribute(layer0_kernel, cudaFuncAttributeMaxDynamicSharedMemorySize, L0_SMEM);
    cudaFuncSetAttribute(layer1_kernel, cudaFuncAttributeMaxDynamicSharedMemorySize, L1_SMEM);
    cudaFuncSetAttribute(layer2_kernel, cudaFuncAttributeMaxDynamicSharedMemorySize, L2_SMEM);

    fps_kernel<<<B_, 1024, FPS_SMEM>>>(xyz);
    prep_kernel<<<(B_ * N_ + 255) / 256, 256>>>(xyz, out, pts_off > 0 ? 1 : 0);
    knn_kernel<<<B_ * 128, 256, KNN_SMEM>>>(xyz);
    layer0_kernel<<<2048, 256, L0_SMEM>>>(xyz, points, w0, b0);
    stats_kernel<<<64, 256>>>(0, 2048, 64, g0, be0);
    layer1_kernel<<<2048, 256, L1_SMEM>>>(w1, b1);
    stats_kernel<<<64, 256>>>(1, 2048, 64, g1, be1);
    layer2_kernel<<<2048, 512, L2_SMEM>>>(w2, b2);
    stats_kernel<<<128, 256>>>(2, 2048, 128, g2, be2);
    pool2_kernel<<<B_ * S_, 128>>>(out, pts_off);
}

// round 10
// speedup vs baseline: 1.2185x; 1.2185x over previous
#include <cuda_runtime.h>
#include <cstdint>

#define FULLMASK 0xffffffffu
typedef unsigned long long ull;
namespace {
constexpr int B_ = 16, N_ = 4096, S_ = 1024, K_ = 32;
constexpr float EPSF = 1e-5f;
constexpr int FPS_SMEM = 3 * N_ * 4;
constexpr int KNN_SMEM = 4 * N_ * 4;
constexpr int L0_SMEM = (68 * 256 + 67 * 64 + 2 * 16 * 65) * 4;   // 95104
constexpr int L1_SMEM = (64 * 256 + 64 * 64 + 2 * 16 * 65) * 4;   // 90240
constexpr int L2_SMEM = (64 * 128 + 64 * 128 + 2 * 8 * 129) * 4;  // 73792
}

// ------------- scratch -------------
__device__ int      g_fps[B_ * S_];
__device__ float    g_newxyz[B_ * S_ * 3];
__device__ float    g_d2[B_ * N_];
__device__ int      g_nn[B_ * S_ * K_];
__device__ float    g_y0[B_ * S_ * K_ * 64];
__device__ float    g_y1[B_ * S_ * K_ * 64];
__device__ float    g_pmax[B_ * S_ * 128];
__device__ float    g_pmin[B_ * S_ * 128];
__device__ float    g_part0[2048 * 128];
__device__ float    g_part1[2048 * 128];
__device__ float    g_part2[4096 * 256];
__device__ float    g_scale0[64], g_shift0[64];
__device__ float    g_scale1[64], g_shift1[64];
__device__ float    g_scale2[128], g_shift2[128];

// ------------- packed fp32x2 helpers (bit-exact: independent IEEE rn lanes) ----
__device__ __forceinline__ ull pack2(float lo, float hi) {
    ull r;
    asm("mov.b64 %0, {%1, %2};" : "=l"(r) : "f"(lo), "f"(hi));
    return r;
}
__device__ __forceinline__ void fma2(ull& d, ull a, ull b) {
    asm("fma.rn.f32x2 %0, %1, %2, %0;" : "+l"(d) : "l"(a), "l"(b));
}
__device__ __forceinline__ ull add2(ull a, ull b) {
    ull r; asm("add.rn.f32x2 %0, %1, %2;" : "=l"(r) : "l"(a), "l"(b)); return r;
}
__device__ __forceinline__ ull mul2(ull a, ull b) {
    ull r; asm("mul.rn.f32x2 %0, %1, %2;" : "=l"(r) : "l"(a), "l"(b)); return r;
}
__device__ __forceinline__ float2 unpack2(ull v) {
    float lo, hi;
    asm("mov.b64 {%0, %1}, %2;" : "=f"(lo), "=f"(hi) : "l"(v));
    return make_float2(lo, hi);
}

// ------------- KNN helpers -------------
__device__ __forceinline__ void cmpswap(float& k, int& v, int j, bool dirAsc, int lane) {
    float ok = __shfl_xor_sync(FULLMASK, k, j);
    int   ov = __shfl_xor_sync(FULLMASK, v, j);
    bool takeOther = (((lane & j) == 0) == dirAsc) ? (ok < k) : (ok > k);
    if (takeOther) { k = ok; v = ov; }
}
__device__ __forceinline__ void bitonic_merge_asc(float& k, int& v, int lane) {
    #pragma unroll
    for (int j = 16; j > 0; j >>= 1) cmpswap(k, v, j, true, lane);
}
__device__ __forceinline__ void bitonic_sort_asc(float& k, int& v, int lane) {
    #pragma unroll
    for (int kk = 2; kk <= 16; kk <<= 1) {
        bool dir = ((lane & kk) == 0);
        #pragma unroll
        for (int j = kk >> 1; j > 0; j >>= 1) cmpswap(k, v, j, dir, lane);
    }
    bitonic_merge_asc(k, v, lane);
}

// ------------- FPS: one CTA per batch, packed f32x2 distance math -------------
__global__ void __launch_bounds__(1024) fps_kernel(const float* __restrict__ xyz) {
    int b = blockIdx.x;
    extern __shared__ float sh[];
    float* sx = sh; float* sy = sh + N_; float* sz = sh + 2 * N_;
    __shared__ unsigned swv[2][32];
    __shared__ unsigned swi[2][32];
    int t = threadIdx.x, w = t >> 5, lane = t & 31;
    const float* X = xyz + (size_t)b * N_ * 3;
    for (int i = t; i < N_; i += 1024) { sx[i] = X[3*i]; sy[i] = X[3*i+1]; sz[i] = X[3*i+2]; }
    __syncthreads();
    ull rxp[2], ryp[2], rzp[2];
    float dist[4];
    #pragma unroll
    for (int p = 0; p < 2; p++) {
        int i0 = t + (2*p) * 1024, i1 = t + (2*p+1) * 1024;
        rxp[p] = pack2(sx[i0], sx[i1]);
        ryp[p] = pack2(sy[i0], sy[i1]);
        rzp[p] = pack2(sz[i0], sz[i1]);
        dist[2*p] = 1e10f; dist[2*p+1] = 1e10f;
    }
    int far = 0;
    for (int it = 0; it < S_; ++it) {
        if (t == 0) g_fps[b * S_ + it] = far;
        float cx = sx[far], cy = sy[far], cz = sz[far];
        ull ncx = pack2(-cx, -cx), ncy = pack2(-cy, -cy), ncz = pack2(-cz, -cz);
        float bv = -1.0f; int bi = 0;
        #pragma unroll
        for (int p = 0; p < 2; p++) {
            ull dx = add2(rxp[p], ncx);
            ull dy = add2(ryp[p], ncy);
            ull dz = add2(rzp[p], ncz);
            ull s = add2(add2(mul2(dx,dx), mul2(dy,dy)), mul2(dz,dz));
            float2 d = unpack2(s);
            float dm0 = fminf(dist[2*p], d.x);   dist[2*p] = dm0;
            if (dm0 > bv) { bv = dm0; bi = t + (2*p) * 1024; }
            float dm1 = fminf(dist[2*p+1], d.y); dist[2*p+1] = dm1;
            if (dm1 > bv) { bv = dm1; bi = t + (2*p+1) * 1024; }
        }
        unsigned db = __float_as_uint(bv);
        unsigned mx = __reduce_max_sync(FULLMASK, db);
        unsigned cand = (db == mx) ? (unsigned)bi : 0xffffffffu;
        unsigned mi = __reduce_min_sync(FULLMASK, cand);
        int buf = it & 1;
        if (lane == 0) { swv[buf][w] = mx; swi[buf][w] = mi; }
        __syncthreads();
        unsigned v2 = swv[buf][lane];
        unsigned i2 = swi[buf][lane];
        unsigned mx2 = __reduce_max_sync(FULLMASK, v2);
        unsigned c2 = (v2 == mx2) ? i2 : 0xffffffffu;
        far = (int)__reduce_min_sync(FULLMASK, c2);
    }
}

// ------------- prep: ||x||^2 + gather new_xyz -------------
__global__ void prep_kernel(const float* __restrict__ xyz, float* __restrict__ out, int write_xyz) {
    int i = blockIdx.x * 256 + threadIdx.x;
    if (i < B_ * N_) {
        float x = xyz[3*i], y = xyz[3*i+1], z = xyz[3*i+2];
        g_d2[i] = __fadd_rn(__fadd_rn(__fmul_rn(x,x), __fmul_rn(y,y)), __fmul_rn(z,z));
    }
    if (i < B_ * S_) {
        int b = i >> 10, n = g_fps[i];
        const float* p = xyz + ((size_t)b * N_ + n) * 3;
        float px = p[0], py = p[1], pz = p[2];
        g_newxyz[3*i] = px; g_newxyz[3*i+1] = py; g_newxyz[3*i+2] = pz;
        if (write_xyz) { out[3*i] = px; out[3*i+1] = py; out[3*i+2] = pz; }
    }
}

// ------------- KNN: warp per query, bitonic + insertion fast-path -------------
__global__ void __launch_bounds__(256) knn_kernel(const float* __restrict__ xyz) {
    extern __shared__ float sh[];
    float* sx = sh; float* sy = sh + N_; float* sz = sh + 2*N_; float* sd = sh + 3*N_;
    int t = threadIdx.x;
    int b = blockIdx.x >> 7;
    int s0 = (blockIdx.x & 127) * 8;
    const float* X = xyz + (size_t)b * N_ * 3;
    for (int i = t; i < N_; i += 256) {
        sx[i] = X[3*i]; sy[i] = X[3*i+1]; sz[i] = X[3*i+2];
        sd[i] = g_d2[b * N_ + i];
    }
    __syncthreads();
    int w = t >> 5, lane = t & 31;
    int q = b * S_ + s0 + w;
    float qx = g_newxyz[3*q], qy = g_newxyz[3*q+1], qz = g_newxyz[3*q+2];
    float q2 = __fadd_rn(__fadd_rn(__fmul_rn(qx,qx), __fmul_rn(qy,qy)), __fmul_rn(qz,qz));
    float key = 3.0e38f; int kid = 0; float curmax = 3.0e38f;
    for (int c = 0; c < N_ / 32; c++) {
        int p = c * 32 + lane;
        float dot = __fadd_rn(__fadd_rn(__fmul_rn(qx, sx[p]),
                                        __fmul_rn(qy, sy[p])),
                              __fmul_rn(qz, sz[p]));
        float d = __fsub_rn(__fadd_rn(q2, sd[p]), __fmul_rn(2.0f, dot));
        unsigned m = __ballot_sync(FULLMASK, d < curmax);
        if (!m) continue;
        if (__popc(m) <= 6) {
            // serial insertion of each surviving candidate into sorted (key,kid)
            while (m) {
                int src = __ffs(m) - 1;
                m &= m - 1;
                float v  = __shfl_sync(FULLMASK, d, src);
                int   vi = __shfl_sync(FULLMASK, p, src);
                if (v < curmax) {
                    unsigned lt = __ballot_sync(FULLMASK, key < v);
                    int pos = __popc(lt);                       // keys ascending => prefix mask
                    float ku = __shfl_up_sync(FULLMASK, key, 1);
                    int   iu = __shfl_up_sync(FULLMASK, kid, 1);
                    if (lane == pos)      { key = v;  kid = vi; }
                    else if (lane > pos)  { key = ku; kid = iu; }
                    curmax = __shfl_sync(FULLMASK, key, 31);
                }
            }
        } else {
            float nk = d; int ni = p;
            bitonic_sort_asc(nk, ni, lane);
            float rk = __shfl_sync(FULLMASK, nk, 31 - lane);
            int   ri = __shfl_sync(FULLMASK, ni, 31 - lane);
            if (rk < key) { key = rk; kid = ri; }
            bitonic_merge_asc(key, kid, lane);
            curmax = __shfl_sync(FULLMASK, key, 31);
        }
    }
    g_nn[q * K_ + lane] = kid;
}

// ================= layer GEMMs: thread tile 16 rows x 8 cols (R8 config) =====

// ------------- layer 0: gather + GEMM 67->64 -------------
__global__ void __launch_bounds__(128, 1) layer0_kernel(const float* __restrict__ xyz,
                                                        const float* __restrict__ points,
                                                        const float* __restrict__ w,
                                                        const float* __restrict__ bias) {
    extern __shared__ float sh[];
    float* XsT = sh;                   // [68][256]
    float* Ws  = XsT + 68 * 256;       // [67][64]
    float* Red = Ws + 67 * 64;         // 2 x [16][65]
    int t = threadIdx.x;
    for (int idx = t; idx < 67 * 64; idx += 128) {
        int cc = idx >> 6, o = idx & 63;
        int c = (cc < 64) ? (cc + 3) : (cc - 64);
        Ws[idx] = w[o * 67 + c];
    }
    #pragma unroll
    for (int rr = 0; rr < 2; rr++) {
        int r = t + rr * 128;
        int gr = blockIdx.x * 256 + r;
        int q = gr >> 5, b = gr >> 15;
        int n = g_nn[gr];
        const float4* prow = (const float4*)(points + ((size_t)b * N_ + n) * 64);
        #pragma unroll 4
        for (int ch = 0; ch < 16; ch++) {
            float4 v = prow[ch];
            XsT[(ch*4+0)*256 + r] = v.x;
            XsT[(ch*4+1)*256 + r] = v.y;
            XsT[(ch*4+2)*256 + r] = v.z;
            XsT[(ch*4+3)*256 + r] = v.w;
        }
        const float* pp = xyz + ((size_t)b * N_ + n) * 3;
        XsT[64*256 + r] = __fadd_rn(pp[0], -g_newxyz[3*q]);
        XsT[65*256 + r] = __fadd_rn(pp[1], -g_newxyz[3*q+1]);
        XsT[66*256 + r] = __fadd_rn(pp[2], -g_newxyz[3*q+2]);
    }
    __syncthreads();
    int rg = t >> 3, cg = t & 7;       // rows rg*16..+15, cols cg*8..+7
    ull acc[8][8];                     // [row-pair][col]
    #pragma unroll
    for (int i = 0; i < 8; i++) {
        float bb = bias[cg*8+i];
        ull bp = pack2(bb, bb);
        #pragma unroll
        for (int p = 0; p < 8; p++) acc[p][i] = bp;
    }
    for (int c = 0; c < 67; c++) {
        const float4* ap = (const float4*)(XsT + c*256 + rg*16);
        float4 a0 = ap[0], a1 = ap[1], a2 = ap[2], a3 = ap[3];
        ull apair[8] = {pack2(a0.x,a0.y), pack2(a0.z,a0.w),
                        pack2(a1.x,a1.y), pack2(a1.z,a1.w),
                        pack2(a2.x,a2.y), pack2(a2.z,a2.w),
                        pack2(a3.x,a3.y), pack2(a3.z,a3.w)};
        const float4* wp = (const float4*)(Ws + c*64 + cg*8);
        float4 w0 = wp[0], w1 = wp[1];
        float wf[8] = {w0.x,w0.y,w0.z,w0.w,w1.x,w1.y,w1.z,w1.w};
        #pragma unroll
        for (int i = 0; i < 8; i++) {
            ull wd = pack2(wf[i], wf[i]);
            #pragma unroll
            for (int p = 0; p < 8; p++) fma2(acc[p][i], apair[p], wd);
        }
    }
    float s1[8], s2[8];
    #pragma unroll
    for (int i = 0; i < 8; i++) { s1[i] = 0.f; s2[i] = 0.f; }
    #pragma unroll
    for (int p = 0; p < 8; p++) {
        float lo[8], hi[8];
        #pragma unroll
        for (int i = 0; i < 8; i++) { float2 v = unpack2(acc[p][i]); lo[i] = v.x; hi[i] = v.y; }
        size_t r0 = (size_t)blockIdx.x * 256 + rg*16 + 2*p;
        float4* d0 = (float4*)(g_y0 + r0 * 64 + cg*8);
        d0[0] = make_float4(lo[0],lo[1],lo[2],lo[3]);
        d0[1] = make_float4(lo[4],lo[5],lo[6],lo[7]);
        float4* d1 = (float4*)(g_y0 + (r0+1) * 64 + cg*8);
        d1[0] = make_float4(hi[0],hi[1],hi[2],hi[3]);
        d1[1] = make_float4(hi[4],hi[5],hi[6],hi[7]);
        #pragma unroll
        for (int i = 0; i < 8; i++) { s1[i] += lo[i]+hi[i]; s2[i] += lo[i]*lo[i]+hi[i]*hi[i]; }
    }
    #pragma unroll
    for (int i = 0; i < 8; i++) {
        int col = cg*8 + i;
        Red[rg*65 + col]        = s1[i];
        Red[1040 + rg*65 + col] = s2[i];
    }
    __syncthreads();
    if (t < 64) {
        float s = 0.f;
        #pragma unroll 4
        for (int j = 0; j < 16; j++) s += Red[j*65 + t];
        g_part0[blockIdx.x*128 + t] = s;
    } else {
        int col = t - 64; float s = 0.f;
        #pragma unroll 4
        for (int j = 0; j < 16; j++) s += Red[1040 + j*65 + col];
        g_part0[blockIdx.x*128 + 64 + col] = s;
    }
}

// ------------- layer 1: BN0+ReLU fused gather, GEMM 64->64 -------------
__global__ void __launch_bounds__(128, 1) layer1_kernel(const float* __restrict__ w,
                                                        const float* __restrict__ bias) {
    extern __shared__ float sh[];
    float* XsT = sh;                   // [64][256]
    float* Ws  = XsT + 64 * 256;       // [64][64]
    float* Red = Ws + 64 * 64;         // 2 x [16][65]
    __shared__ float sS[64], sH[64];
    int t = threadIdx.x;
    if (t < 64) { sS[t] = g_scale0[t]; sH[t] = g_shift0[t]; }
    for (int idx = t; idx < 64 * 64; idx += 128) {
        int c = idx >> 6, o = idx & 63;
        Ws[idx] = w[o * 64 + c];
    }
    __syncthreads();
    #pragma unroll
    for (int rr = 0; rr < 2; rr++) {
        int r = t + rr * 128;
        size_t gr = (size_t)blockIdx.x * 256 + r;
        const float4* src = (const float4*)(g_y0 + gr * 64);
        #pragma unroll 4
        for (int ch = 0; ch < 16; ch++) {
            float4 v = src[ch]; int c0 = ch * 4;
            XsT[(c0+0)*256 + r] = fmaxf(0.f, fmaf(v.x, sS[c0],   sH[c0]));
            XsT[(c0+1)*256 + r] = fmaxf(0.f, fmaf(v.y, sS[c0+1], sH[c0+1]));
            XsT[(c0+2)*256 + r] = fmaxf(0.f, fmaf(v.z, sS[c0+2], sH[c0+2]));
            XsT[(c0+3)*256 + r] = fmaxf(0.f, fmaf(v.w, sS[c0+3], sH[c0+3]));
        }
    }
    __syncthreads();
    int rg = t >> 3, cg = t & 7;
    ull acc[8][8];
    #pragma unroll
    for (int i = 0; i < 8; i++) {
        float bb = bias[cg*8+i];
        ull bp = pack2(bb, bb);
        #pragma unroll
        for (int p = 0; p < 8; p++) acc[p][i] = bp;
    }
    for (int c = 0; c < 64; c++) {
        const float4* ap = (const float4*)(XsT + c*256 + rg*16);
        float4 a0 = ap[0], a1 = ap[1], a2 = ap[2], a3 = ap[3];
        ull apair[8] = {pack2(a0.x,a0.y), pack2(a0.z,a0.w),
                        pack2(a1.x,a1.y), pack2(a1.z,a1.w),
                        pack2(a2.x,a2.y), pack2(a2.z,a2.w),
                        pack2(a3.x,a3.y), pack2(a3.z,a3.w)};
        const float4* wp = (const float4*)(Ws + c*64 + cg*8);
        float4 w0 = wp[0], w1 = wp[1];
        float wf[8] = {w0.x,w0.y,w0.z,w0.w,w1.x,w1.y,w1.z,w1.w};
        #pragma unroll
        for (int i = 0; i < 8; i++) {
            ull wd = pack2(wf[i], wf[i]);
            #pragma unroll
            for (int p = 0; p < 8; p++) fma2(acc[p][i], apair[p], wd);
        }
    }
    float s1[8], s2[8];
    #pragma unroll
    for (int i = 0; i < 8; i++) { s1[i] = 0.f; s2[i] = 0.f; }
    #pragma unroll
    for (int p = 0; p < 8; p++) {
        float lo[8], hi[8];
        #pragma unroll
        for (int i = 0; i < 8; i++) { float2 v = unpack2(acc[p][i]); lo[i] = v.x; hi[i] = v.y; }
        size_t r0 = (size_t)blockIdx.x * 256 + rg*16 + 2*p;
        float4* d0 = (float4*)(g_y1 + r0 * 64 + cg*8);
        d0[0] = make_float4(lo[0],lo[1],lo[2],lo[3]);
        d0[1] = make_float4(lo[4],lo[5],lo[6],lo[7]);
        float4* d1 = (float4*)(g_y1 + (r0+1) * 64 + cg*8);
        d1[0] = make_float4(hi[0],hi[1],hi[2],hi[3]);
        d1[1] = make_float4(hi[4],hi[5],hi[6],hi[7]);
        #pragma unroll
        for (int i = 0; i < 8; i++) { s1[i] += lo[i]+hi[i]; s2[i] += lo[i]*lo[i]+hi[i]*hi[i]; }
    }
    #pragma unroll
    for (int i = 0; i < 8; i++) {
        int col = cg*8 + i;
        Red[rg*65 + col]        = s1[i];
        Red[1040 + rg*65 + col] = s2[i];
    }
    __syncthreads();
    if (t < 64) {
        float s = 0.f;
        #pragma unroll 4
        for (int j = 0; j < 16; j++) s += Red[j*65 + t];
        g_part1[blockIdx.x*128 + t] = s;
    } else {
        int col = t - 64; float s = 0.f;
        #pragma unroll 4
        for (int j = 0; j < 16; j++) s += Red[1040 + j*65 + col];
        g_part1[blockIdx.x*128 + 64 + col] = s;
    }
}

// ------------- layer 2 fused: 128-row block, 128 thr, 16x8 tile, max/min -------
__global__ void __launch_bounds__(128, 1) layer2_kernel(const float* __restrict__ w,
                                                        const float* __restrict__ bias) {
    extern __shared__ float sh[];
    float* XsT = sh;                   // [64][128]
    float* Ws  = XsT + 64 * 128;       // [64][128]
    float* Red = Ws + 64 * 128;        // 2 x [8][129]
    __shared__ float sS[64], sH[64];
    int t = threadIdx.x;
    if (t < 64) { sS[t] = g_scale1[t]; sH[t] = g_shift1[t]; }
    for (int idx = t; idx < 64 * 128; idx += 128) {
        int c = idx >> 7, o = idx & 127;
        Ws[idx] = w[o * 64 + c];
    }
    __syncthreads();
    {
        int r = t;
        size_t gr = (size_t)blockIdx.x * 128 + r;
        const float4* src = (const float4*)(g_y1 + gr * 64);
        #pragma unroll 4
        for (int ch = 0; ch < 16; ch++) {
            float4 v = src[ch]; int c0 = ch * 4;
            XsT[(c0+0)*128 + r] = fmaxf(0.f, fmaf(v.x, sS[c0],   sH[c0]));
            XsT[(c0+1)*128 + r] = fmaxf(0.f, fmaf(v.y, sS[c0+1], sH[c0+1]));
            XsT[(c0+2)*128 + r] = fmaxf(0.f, fmaf(v.z, sS[c0+2], sH[c0+2]));
            XsT[(c0+3)*128 + r] = fmaxf(0.f, fmaf(v.w, sS[c0+3], sH[c0+3]));
        }
    }
    __syncthreads();
    int rg = t >> 4, cg = t & 15;      // rows rg*16..+15 (of 128), cols cg*8..+7 (of 128)
    ull acc[8][8];
    #pragma unroll
    for (int i = 0; i < 8; i++) {
        float bb = bias[cg*8+i];
        ull bp = pack2(bb, bb);
        #pragma unroll
        for (int p = 0; p < 8; p++) acc[p][i] = bp;
    }
    for (int c = 0; c < 64; c++) {
        const float4* ap = (const float4*)(XsT + c*128 + rg*16);
        float4 a0 = ap[0], a1 = ap[1], a2 = ap[2], a3 = ap[3];
        ull apair[8] = {pack2(a0.x,a0.y), pack2(a0.z,a0.w),
                        pack2(a1.x,a1.y), pack2(a1.z,a1.w),
                        pack2(a2.x,a2.y), pack2(a2.z,a2.w),
                        pack2(a3.x,a3.y), pack2(a3.z,a3.w)};
        const float4* wp = (const float4*)(Ws + c*128 + cg*8);
        float4 w0 = wp[0], w1 = wp[1];
        float wf[8] = {w0.x,w0.y,w0.z,w0.w,w1.x,w1.y,w1.z,w1.w};
        #pragma unroll
        for (int i = 0; i < 8; i++) {
            ull wd = pack2(wf[i], wf[i]);
            #pragma unroll
            for (int p = 0; p < 8; p++) fma2(acc[p][i], apair[p], wd);
        }
    }
    // stats + max/min over this thread's 16 rows (all within (b,s) group rg>>1)
    float s1[8], s2[8], mx[8], mn[8];
    #pragma unroll
    for (int i = 0; i < 8; i++) { s1[i]=0.f; s2[i]=0.f; mx[i]=-3.4e38f; mn[i]=3.4e38f; }
    #pragma unroll
    for (int p = 0; p < 8; p++) {
        #pragma unroll
        for (int i = 0; i < 8; i++) {
            float2 v = unpack2(acc[p][i]);
            s1[i] += v.x + v.y;
            s2[i] += v.x*v.x + v.y*v.y;
            mx[i] = fmaxf(mx[i], fmaxf(v.x, v.y));
            mn[i] = fminf(mn[i], fminf(v.x, v.y));
        }
    }
    #pragma unroll
    for (int i = 0; i < 8; i++) {
        int col = cg*8 + i;
        Red[rg*129 + col]        = s1[i];
        Red[1032 + rg*129 + col] = s2[i];
    }
    __syncthreads();
    {
        int col = t;   // 0..127
        float sa = 0.f, sb = 0.f;
        #pragma unroll
        for (int j = 0; j < 8; j++) { sa += Red[j*129 + col]; sb += Red[1032 + j*129 + col]; }
        g_part2[blockIdx.x*256 + col] = sa;
        g_part2[blockIdx.x*256 + 128 + col] = sb;
    }
    __syncthreads();
    #pragma unroll
    for (int i = 0; i < 8; i++) {
        int col = cg*8 + i;
        Red[rg*129 + col]        = mx[i];
        Red[1032 + rg*129 + col] = mn[i];
    }
    __syncthreads();
    {
        // 4 (b,s) groups of 32 rows: group g combines rg 2g, 2g+1
        int col = t;   // 0..127
        #pragma unroll
        for (int g = 0; g < 4; g++) {
            size_t bs = (size_t)blockIdx.x * 4 + g;
            float m = fmaxf(Red[(2*g)*129 + col], Red[(2*g+1)*129 + col]);
            float n = fminf(Red[1032 + (2*g)*129 + col], Red[1032 + (2*g+1)*129 + col]);
            g_pmax[bs*128 + col] = m;
            g_pmin[bs*128 + col] = n;
        }
    }
}

// ------------- BN stats -------------
__global__ void __launch_bounds__(256) stats_kernel(int layer, int nblk, int C,
                             const float* __restrict__ gamma, const float* __restrict__ beta) {
    int c = blockIdx.x;
    int t = threadIdx.x;
    const float* part = (layer == 0) ? g_part0 : (layer == 1) ? g_part1 : g_part2;
    float s1 = 0.f, s2 = 0.f;
    for (int bk = t; bk < nblk; bk += 256) {
        s1 += part[(size_t)bk*2*C + c];
        s2 += part[(size_t)bk*2*C + C + c];
    }
    __shared__ float r1[256], r2[256];
    r1[t] = s1; r2[t] = s2;
    __syncthreads();
    for (int off = 128; off >= 1; off >>= 1) {
        if (t < off) { r1[t] += r1[t+off]; r2[t] += r2[t+off]; }
        __syncthreads();
    }
    if (t == 0) {
        const float n = 524288.f;
        float mean = r1[0] / n;
        float var = r2[0] / n - mean * mean;
        float sc = gamma[c] * rsqrtf(var + EPSF);
        float sf = beta[c] - mean * sc;
        if (layer == 0)      { g_scale0[c] = sc; g_shift0[c] = sf; }
        else if (layer == 1) { g_scale1[c] = sc; g_shift1[c] = sf; }
        else                 { g_scale2[c] = sc; g_shift2[c] = sf; }
    }
}

// ------------- pool epilogue -------------
__global__ void pool2_kernel(float* __restrict__ out, int pts_off) {
    int bs = blockIdx.x;
    int c = threadIdx.x;
    float sc = g_scale2[c], sf = g_shift2[c];
    float v = (sc >= 0.f) ? g_pmax[(size_t)bs*128 + c] : g_pmin[(size_t)bs*128 + c];
    float m = fmaxf(fmaf(v, sc, sf), 0.f);
    out[pts_off + (bs >> 10) * (128 * 1024) + c * 1024 + (bs & 1023)] = m;
}

extern "C" void kernel_launch(void* const* d_in, const int* in_sizes, int n_in,
                              void* d_out, int out_size) {
    const float* xyz    = (const float*)d_in[0];
    const float* points = (const float*)d_in[1];
    const float* w0 = (const float*)d_in[2];  const float* b0  = (const float*)d_in[3];
    const float* g0 = (const float*)d_in[4];  const float* be0 = (const float*)d_in[5];
    const float* w1 = (const float*)d_in[6];  const float* b1  = (const float*)d_in[7];
    const float* g1 = (const float*)d_in[8];  const float* be1 = (const float*)d_in[9];
    const float* w2 = (const float*)d_in[10]; const float* b2  = (const float*)d_in[11];
    const float* g2 = (const float*)d_in[12]; const float* be2 = (const float*)d_in[13];
    float* out = (float*)d_out;

    int npts = B_ * 128 * S_;
    int pts_off = out_size - npts;
    if (pts_off < 0) pts_off = 0;

    cudaFuncSetAttribute(fps_kernel,    cudaFuncAttributeMaxDynamicSharedMemorySize, FPS_SMEM);
    cudaFuncSetAttribute(knn_kernel,    cudaFuncAttributeMaxDynamicSharedMemorySize, KNN_SMEM);
    cudaFuncSetAttribute(layer0_kernel, cudaFuncAttributeMaxDynamicSharedMemorySize, L0_SMEM);
    cudaFuncSetAttribute(layer1_kernel, cudaFuncAttributeMaxDynamicSharedMemorySize, L1_SMEM);
    cudaFuncSetAttribute(layer2_kernel, cudaFuncAttributeMaxDynamicSharedMemorySize, L2_SMEM);

    fps_kernel<<<B_, 1024, FPS_SMEM>>>(xyz);
    prep_kernel<<<(B_ * N_ + 255) / 256, 256>>>(xyz, out, pts_off > 0 ? 1 : 0);
    knn_kernel<<<B_ * 128, 256, KNN_SMEM>>>(xyz);
    layer0_kernel<<<2048, 128, L0_SMEM>>>(xyz, points, w0, b0);
    stats_kernel<<<64, 256>>>(0, 2048, 64, g0, be0);
    layer1_kernel<<<2048, 128, L1_SMEM>>>(w1, b1);
    stats_kernel<<<64, 256>>>(1, 2048, 64, g1, be1);
    layer2_kernel<<<4096, 128, L2_SMEM>>>(w2, b2);
    stats_kernel<<<128, 256>>>(2, 4096, 128, g2, be2);
    pool2_kernel<<<B_ * S_, 128>>>(out, pts_off);
}

// round 11
// speedup vs baseline: 1.3301x; 1.0915x over previous
#include <cuda_runtime.h>
#include <cstdint>

#define FULLMASK 0xffffffffu
typedef unsigned long long ull;
namespace {
constexpr int B_ = 16, N_ = 4096, S_ = 1024, K_ = 32;
constexpr float EPSF = 1e-5f;
constexpr int FPS_SMEM = 3 * N_ * 4;
constexpr int KNN_SMEM = 4 * N_ * 4;
constexpr int LA_SMEM = (64 * 256 + 64 * 64) * 4;                 // 81920 (gemmP)
constexpr int L1_SMEM = (64 * 256 + 64 * 64 + 2 * 16 * 65) * 4;   // 90240
constexpr int L2_SMEM = (64 * 128 + 64 * 128 + 2 * 8 * 129) * 4;  // 73792
}

// ------------- scratch -------------
__device__ int      g_fps[B_ * S_];
__device__ float    g_newxyz[B_ * S_ * 3];
__device__ float    g_d2[B_ * N_];
__device__ int      g_nn[B_ * S_ * K_];
__device__ float    g_P[B_ * N_ * 64];          // W0[:,3:]·points + b0, per point
__device__ float    g_y0[B_ * S_ * K_ * 64];
__device__ float    g_y1[B_ * S_ * K_ * 64];
__device__ float    g_pmax[B_ * S_ * 128];
__device__ float    g_pmin[B_ * S_ * 128];
__device__ float    g_part0[16384 * 128];
__device__ float    g_part1[2048 * 128];
__device__ float    g_part2[4096 * 256];
__device__ float    g_scale0[64], g_shift0[64];
__device__ float    g_scale1[64], g_shift1[64];
__device__ float    g_scale2[128], g_shift2[128];

// ------------- packed fp32x2 helpers (bit-exact: independent IEEE rn lanes) ----
__device__ __forceinline__ ull pack2(float lo, float hi) {
    ull r;
    asm("mov.b64 %0, {%1, %2};" : "=l"(r) : "f"(lo), "f"(hi));
    return r;
}
__device__ __forceinline__ void fma2(ull& d, ull a, ull b) {
    asm("fma.rn.f32x2 %0, %1, %2, %0;" : "+l"(d) : "l"(a), "l"(b));
}
__device__ __forceinline__ ull add2(ull a, ull b) {
    ull r; asm("add.rn.f32x2 %0, %1, %2;" : "=l"(r) : "l"(a), "l"(b)); return r;
}
__device__ __forceinline__ ull mul2(ull a, ull b) {
    ull r; asm("mul.rn.f32x2 %0, %1, %2;" : "=l"(r) : "l"(a), "l"(b)); return r;
}
__device__ __forceinline__ float2 unpack2(ull v) {
    float lo, hi;
    asm("mov.b64 {%0, %1}, %2;" : "=f"(lo), "=f"(hi) : "l"(v));
    return make_float2(lo, hi);
}

// ------------- KNN helpers -------------
__device__ __forceinline__ void cmpswap(float& k, int& v, int j, bool dirAsc, int lane) {
    float ok = __shfl_xor_sync(FULLMASK, k, j);
    int   ov = __shfl_xor_sync(FULLMASK, v, j);
    bool takeOther = (((lane & j) == 0) == dirAsc) ? (ok < k) : (ok > k);
    if (takeOther) { k = ok; v = ov; }
}
__device__ __forceinline__ void bitonic_merge_asc(float& k, int& v, int lane) {
    #pragma unroll
    for (int j = 16; j > 0; j >>= 1) cmpswap(k, v, j, true, lane);
}
__device__ __forceinline__ void bitonic_sort_asc(float& k, int& v, int lane) {
    #pragma unroll
    for (int kk = 2; kk <= 16; kk <<= 1) {
        bool dir = ((lane & kk) == 0);
        #pragma unroll
        for (int j = kk >> 1; j > 0; j >>= 1) cmpswap(k, v, j, dir, lane);
    }
    bitonic_merge_asc(k, v, lane);
}

// ------------- FPS + fused prep tail -------------
__global__ void __launch_bounds__(1024) fps_kernel(const float* __restrict__ xyz,
                                                   float* __restrict__ out, int write_xyz) {
    int b = blockIdx.x;
    extern __shared__ float sh[];
    float* sx = sh; float* sy = sh + N_; float* sz = sh + 2 * N_;
    __shared__ unsigned swv[2][32];
    __shared__ unsigned swi[2][32];
    int t = threadIdx.x, w = t >> 5, lane = t & 31;
    const float* X = xyz + (size_t)b * N_ * 3;
    for (int i = t; i < N_; i += 1024) { sx[i] = X[3*i]; sy[i] = X[3*i+1]; sz[i] = X[3*i+2]; }
    __syncthreads();
    ull rxp[2], ryp[2], rzp[2];
    float dist[4];
    #pragma unroll
    for (int p = 0; p < 2; p++) {
        int i0 = t + (2*p) * 1024, i1 = t + (2*p+1) * 1024;
        rxp[p] = pack2(sx[i0], sx[i1]);
        ryp[p] = pack2(sy[i0], sy[i1]);
        rzp[p] = pack2(sz[i0], sz[i1]);
        dist[2*p] = 1e10f; dist[2*p+1] = 1e10f;
    }
    int far = 0;
    for (int it = 0; it < S_; ++it) {
        if (t == 0) g_fps[b * S_ + it] = far;
        float cx = sx[far], cy = sy[far], cz = sz[far];
        ull ncx = pack2(-cx, -cx), ncy = pack2(-cy, -cy), ncz = pack2(-cz, -cz);
        float bv = -1.0f; int bi = 0;
        #pragma unroll
        for (int p = 0; p < 2; p++) {
            ull dx = add2(rxp[p], ncx);
            ull dy = add2(ryp[p], ncy);
            ull dz = add2(rzp[p], ncz);
            ull s = add2(add2(mul2(dx,dx), mul2(dy,dy)), mul2(dz,dz));
            float2 d = unpack2(s);
            float dm0 = fminf(dist[2*p], d.x);   dist[2*p] = dm0;
            if (dm0 > bv) { bv = dm0; bi = t + (2*p) * 1024; }
            float dm1 = fminf(dist[2*p+1], d.y); dist[2*p+1] = dm1;
            if (dm1 > bv) { bv = dm1; bi = t + (2*p+1) * 1024; }
        }
        unsigned db = __float_as_uint(bv);
        unsigned mx = __reduce_max_sync(FULLMASK, db);
        unsigned cand = (db == mx) ? (unsigned)bi : 0xffffffffu;
        unsigned mi = __reduce_min_sync(FULLMASK, cand);
        int buf = it & 1;
        if (lane == 0) { swv[buf][w] = mx; swi[buf][w] = mi; }
        __syncthreads();
        unsigned v2 = swv[buf][lane];
        unsigned i2 = swi[buf][lane];
        unsigned mx2 = __reduce_max_sync(FULLMASK, v2);
        unsigned c2 = (v2 == mx2) ? i2 : 0xffffffffu;
        far = (int)__reduce_min_sync(FULLMASK, c2);
    }
    __syncthreads();   // make g_fps writes (thread 0) visible block-wide
    // fused prep: ||x||^2 for all points + gather new_xyz for this batch
    #pragma unroll
    for (int r = 0; r < 4; r++) {
        int i = t + r * 1024;
        float x = sx[i], y = sy[i], z = sz[i];
        g_d2[b * N_ + i] = __fadd_rn(__fadd_rn(__fmul_rn(x,x), __fmul_rn(y,y)), __fmul_rn(z,z));
    }
    {
        int i = t;         // 1024 threads == S_
        int n = g_fps[b * S_ + i];
        float px = sx[n], py = sy[n], pz = sz[n];
        int gi = b * S_ + i;
        g_newxyz[3*gi] = px; g_newxyz[3*gi+1] = py; g_newxyz[3*gi+2] = pz;
        if (write_xyz) { out[3*gi] = px; out[3*gi+1] = py; out[3*gi+2] = pz; }
    }
}

// ------------- KNN: warp per query, bitonic + insertion fast-path -------------
__global__ void __launch_bounds__(256) knn_kernel(const float* __restrict__ xyz) {
    extern __shared__ float sh[];
    float* sx = sh; float* sy = sh + N_; float* sz = sh + 2*N_; float* sd = sh + 3*N_;
    int t = threadIdx.x;
    int b = blockIdx.x >> 7;
    int s0 = (blockIdx.x & 127) * 8;
    const float* X = xyz + (size_t)b * N_ * 3;
    for (int i = t; i < N_; i += 256) {
        sx[i] = X[3*i]; sy[i] = X[3*i+1]; sz[i] = X[3*i+2];
        sd[i] = g_d2[b * N_ + i];
    }
    __syncthreads();
    int w = t >> 5, lane = t & 31;
    int q = b * S_ + s0 + w;
    float qx = g_newxyz[3*q], qy = g_newxyz[3*q+1], qz = g_newxyz[3*q+2];
    float q2 = __fadd_rn(__fadd_rn(__fmul_rn(qx,qx), __fmul_rn(qy,qy)), __fmul_rn(qz,qz));
    float key = 3.0e38f; int kid = 0; float curmax = 3.0e38f;
    for (int c = 0; c < N_ / 32; c++) {
        int p = c * 32 + lane;
        float dot = __fadd_rn(__fadd_rn(__fmul_rn(qx, sx[p]),
                                        __fmul_rn(qy, sy[p])),
                              __fmul_rn(qz, sz[p]));
        float d = __fsub_rn(__fadd_rn(q2, sd[p]), __fmul_rn(2.0f, dot));
        unsigned m = __ballot_sync(FULLMASK, d < curmax);
        if (!m) continue;
        if (__popc(m) <= 6) {
            while (m) {
                int src = __ffs(m) - 1;
                m &= m - 1;
                float v  = __shfl_sync(FULLMASK, d, src);
                int   vi = __shfl_sync(FULLMASK, p, src);
                if (v < curmax) {
                    unsigned lt = __ballot_sync(FULLMASK, key < v);
                    int pos = __popc(lt);
                    float ku = __shfl_up_sync(FULLMASK, key, 1);
                    int   iu = __shfl_up_sync(FULLMASK, kid, 1);
                    if (lane == pos)      { key = v;  kid = vi; }
                    else if (lane > pos)  { key = ku; kid = iu; }
                    curmax = __shfl_sync(FULLMASK, key, 31);
                }
            }
        } else {
            float nk = d; int ni = p;
            bitonic_sort_asc(nk, ni, lane);
            float rk = __shfl_sync(FULLMASK, nk, 31 - lane);
            int   ri = __shfl_sync(FULLMASK, ni, 31 - lane);
            if (rk < key) { key = rk; kid = ri; }
            bitonic_merge_asc(key, kid, lane);
            curmax = __shfl_sync(FULLMASK, key, 31);
        }
    }
    g_nn[q * K_ + lane] = kid;
}

// ------------- kernel A: P = W0[:,3:]·points + b0, per point (65536 rows) ------
__global__ void __launch_bounds__(128, 1) gemmP_kernel(const float* __restrict__ points,
                                                       const float* __restrict__ w,
                                                       const float* __restrict__ bias) {
    extern __shared__ float sh[];
    float* XsT = sh;                   // [64][256]
    float* Ws  = XsT + 64 * 256;       // [64][64]
    int t = threadIdx.x;
    for (int idx = t; idx < 64 * 64; idx += 128) {
        int c = idx >> 6, o = idx & 63;
        Ws[idx] = w[o * 67 + 3 + c];
    }
    #pragma unroll
    for (int rr = 0; rr < 2; rr++) {
        int r = t + rr * 128;
        size_t gr = (size_t)blockIdx.x * 256 + r;     // (b,n) row, coalesced
        const float4* src = (const float4*)(points + gr * 64);
        #pragma unroll 4
        for (int ch = 0; ch < 16; ch++) {
            float4 v = src[ch];
            XsT[(ch*4+0)*256 + r] = v.x;
            XsT[(ch*4+1)*256 + r] = v.y;
            XsT[(ch*4+2)*256 + r] = v.z;
            XsT[(ch*4+3)*256 + r] = v.w;
        }
    }
    __syncthreads();
    int rg = t >> 3, cg = t & 7;       // rows rg*16..+15, cols cg*8..+7
    ull acc[8][8];
    #pragma unroll
    for (int i = 0; i < 8; i++) {
        float bb = bias[cg*8+i];
        ull bp = pack2(bb, bb);
        #pragma unroll
        for (int p = 0; p < 8; p++) acc[p][i] = bp;
    }
    for (int c = 0; c < 64; c++) {
        const float4* ap = (const float4*)(XsT + c*256 + rg*16);
        float4 a0 = ap[0], a1 = ap[1], a2 = ap[2], a3 = ap[3];
        ull apair[8] = {pack2(a0.x,a0.y), pack2(a0.z,a0.w),
                        pack2(a1.x,a1.y), pack2(a1.z,a1.w),
                        pack2(a2.x,a2.y), pack2(a2.z,a2.w),
                        pack2(a3.x,a3.y), pack2(a3.z,a3.w)};
        const float4* wp = (const float4*)(Ws + c*64 + cg*8);
        float4 w0 = wp[0], w1 = wp[1];
        float wf[8] = {w0.x,w0.y,w0.z,w0.w,w1.x,w1.y,w1.z,w1.w};
        #pragma unroll
        for (int i = 0; i < 8; i++) {
            ull wd = pack2(wf[i], wf[i]);
            #pragma unroll
            for (int p = 0; p < 8; p++) fma2(acc[p][i], apair[p], wd);
        }
    }
    #pragma unroll
    for (int p = 0; p < 8; p++) {
        float lo[8], hi[8];
        #pragma unroll
        for (int i = 0; i < 8; i++) { float2 v = unpack2(acc[p][i]); lo[i] = v.x; hi[i] = v.y; }
        size_t r0 = (size_t)blockIdx.x * 256 + rg*16 + 2*p;
        float4* d0 = (float4*)(g_P + r0 * 64 + cg*8);
        d0[0] = make_float4(lo[0],lo[1],lo[2],lo[3]);
        d0[1] = make_float4(lo[4],lo[5],lo[6],lo[7]);
        float4* d1 = (float4*)(g_P + (r0+1) * 64 + cg*8);
        d1[0] = make_float4(hi[0],hi[1],hi[2],hi[3]);
        d1[1] = make_float4(hi[4],hi[5],hi[6],hi[7]);
    }
}

// ------------- kernel B: y0 = P[n] + xyz_diff·W0[:,0:3], + BN0 stats -----------
__global__ void __launch_bounds__(256) layer0b_kernel(const float* __restrict__ xyz,
                                                      const float* __restrict__ w) {
    __shared__ float sw[3 * 64];
    __shared__ float Red[2 * 2080];    // 2 x [32][65]
    int t = threadIdx.x;
    if (t < 192) {
        int k = t >> 6, o = t & 63;
        sw[k * 64 + o] = w[o * 67 + k];
    }
    __syncthreads();
    int rg = t >> 3, cg = t & 7;       // 32 rows x 8 col-groups
    int gr = blockIdx.x * 32 + rg;
    int q = gr >> 5, b = gr >> 15;
    int n = g_nn[gr];
    const float* pp = xyz + ((size_t)b * N_ + n) * 3;
    float dx = __fadd_rn(pp[0], -g_newxyz[3*q]);
    float dy = __fadd_rn(pp[1], -g_newxyz[3*q+1]);
    float dz = __fadd_rn(pp[2], -g_newxyz[3*q+2]);
    const float4* Pp = (const float4*)(g_P + ((size_t)b * N_ + n) * 64) + cg * 2;
    float4 p0 = Pp[0], p1 = Pp[1];
    float y[8] = {p0.x,p0.y,p0.z,p0.w,p1.x,p1.y,p1.z,p1.w};
    float s1 = 0.f;
    #pragma unroll
    for (int i = 0; i < 8; i++) {
        int o = cg*8 + i;
        float v = fmaf(dz, sw[128+o], fmaf(dy, sw[64+o], fmaf(dx, sw[o], y[i])));
        y[i] = v;
        s1 += v;
    }
    float4* dst = (float4*)(g_y0 + (size_t)gr * 64 + cg * 8);
    dst[0] = make_float4(y[0],y[1],y[2],y[3]);
    dst[1] = make_float4(y[4],y[5],y[6],y[7]);
    // stats: per thread, one row, 8 cols
    #pragma unroll
    for (int i = 0; i < 8; i++) Red[rg*65 + cg*8 + i] = y[i];
    __syncthreads();
    if (t < 64) {
        float s = 0.f;
        #pragma unroll 8
        for (int j = 0; j < 32; j++) s += Red[j*65 + t];
        g_part0[(size_t)blockIdx.x*128 + t] = s;
    }
    __syncthreads();
    #pragma unroll
    for (int i = 0; i < 8; i++) Red[rg*65 + cg*8 + i] = y[i]*y[i];
    __syncthreads();
    if (t < 64) {
        float s = 0.f;
        #pragma unroll 8
        for (int j = 0; j < 32; j++) s += Red[j*65 + t];
        g_part0[(size_t)blockIdx.x*128 + 64 + t] = s;
    }
}

// ------------- layer 1: BN0+ReLU fused gather, GEMM 64->64 -------------
__global__ void __launch_bounds__(128, 1) layer1_kernel(const float* __restrict__ w,
                                                        const float* __restrict__ bias) {
    extern __shared__ float sh[];
    float* XsT = sh;                   // [64][256]
    float* Ws  = XsT + 64 * 256;       // [64][64]
    float* Red = Ws + 64 * 64;         // 2 x [16][65]
    __shared__ float sS[64], sH[64];
    int t = threadIdx.x;
    if (t < 64) { sS[t] = g_scale0[t]; sH[t] = g_shift0[t]; }
    for (int idx = t; idx < 64 * 64; idx += 128) {
        int c = idx >> 6, o = idx & 63;
        Ws[idx] = w[o * 64 + c];
    }
    __syncthreads();
    #pragma unroll
    for (int rr = 0; rr < 2; rr++) {
        int r = t + rr * 128;
        size_t gr = (size_t)blockIdx.x * 256 + r;
        const float4* src = (const float4*)(g_y0 + gr * 64);
        #pragma unroll 4
        for (int ch = 0; ch < 16; ch++) {
            float4 v = src[ch]; int c0 = ch * 4;
            XsT[(c0+0)*256 + r] = fmaxf(0.f, fmaf(v.x, sS[c0],   sH[c0]));
            XsT[(c0+1)*256 + r] = fmaxf(0.f, fmaf(v.y, sS[c0+1], sH[c0+1]));
            XsT[(c0+2)*256 + r] = fmaxf(0.f, fmaf(v.z, sS[c0+2], sH[c0+2]));
            XsT[(c0+3)*256 + r] = fmaxf(0.f, fmaf(v.w, sS[c0+3], sH[c0+3]));
        }
    }
    __syncthreads();
    int rg = t >> 3, cg = t & 7;
    ull acc[8][8];
    #pragma unroll
    for (int i = 0; i < 8; i++) {
        float bb = bias[cg*8+i];
        ull bp = pack2(bb, bb);
        #pragma unroll
        for (int p = 0; p < 8; p++) acc[p][i] = bp;
    }
    for (int c = 0; c < 64; c++) {
        const float4* ap = (const float4*)(XsT + c*256 + rg*16);
        float4 a0 = ap[0], a1 = ap[1], a2 = ap[2], a3 = ap[3];
        ull apair[8] = {pack2(a0.x,a0.y), pack2(a0.z,a0.w),
                        pack2(a1.x,a1.y), pack2(a1.z,a1.w),
                        pack2(a2.x,a2.y), pack2(a2.z,a2.w),
                        pack2(a3.x,a3.y), pack2(a3.z,a3.w)};
        const float4* wp = (const float4*)(Ws + c*64 + cg*8);
        float4 w0 = wp[0], w1 = wp[1];
        float wf[8] = {w0.x,w0.y,w0.z,w0.w,w1.x,w1.y,w1.z,w1.w};
        #pragma unroll
        for (int i = 0; i < 8; i++) {
            ull wd = pack2(wf[i], wf[i]);
            #pragma unroll
            for (int p = 0; p < 8; p++) fma2(acc[p][i], apair[p], wd);
        }
    }
    float s1[8], s2[8];
    #pragma unroll
    for (int i = 0; i < 8; i++) { s1[i] = 0.f; s2[i] = 0.f; }
    #pragma unroll
    for (int p = 0; p < 8; p++) {
        float lo[8], hi[8];
        #pragma unroll
        for (int i = 0; i < 8; i++) { float2 v = unpack2(acc[p][i]); lo[i] = v.x; hi[i] = v.y; }
        size_t r0 = (size_t)blockIdx.x * 256 + rg*16 + 2*p;
        float4* d0 = (float4*)(g_y1 + r0 * 64 + cg*8);
        d0[0] = make_float4(lo[0],lo[1],lo[2],lo[3]);
        d0[1] = make_float4(lo[4],lo[5],lo[6],lo[7]);
        float4* d1 = (float4*)(g_y1 + (r0+1) * 64 + cg*8);
        d1[0] = make_float4(hi[0],hi[1],hi[2],hi[3]);
        d1[1] = make_float4(hi[4],hi[5],hi[6],hi[7]);
        #pragma unroll
        for (int i = 0; i < 8; i++) { s1[i] += lo[i]+hi[i]; s2[i] += lo[i]*lo[i]+hi[i]*hi[i]; }
    }
    #pragma unroll
    for (int i = 0; i < 8; i++) {
        int col = cg*8 + i;
        Red[rg*65 + col]        = s1[i];
        Red[1040 + rg*65 + col] = s2[i];
    }
    __syncthreads();
    if (t < 64) {
        float s = 0.f;
        #pragma unroll 4
        for (int j = 0; j < 16; j++) s += Red[j*65 + t];
        g_part1[blockIdx.x*128 + t] = s;
    } else {
        int col = t - 64; float s = 0.f;
        #pragma unroll 4
        for (int j = 0; j < 16; j++) s += Red[1040 + j*65 + col];
        g_part1[blockIdx.x*128 + 64 + col] = s;
    }
}

// ------------- layer 2 fused: 128-row block, 128 thr, 16x8 tile, max/min -------
__global__ void __launch_bounds__(128, 1) layer2_kernel(const float* __restrict__ w,
                                                        const float* __restrict__ bias) {
    extern __shared__ float sh[];
    float* XsT = sh;                   // [64][128]
    float* Ws  = XsT + 64 * 128;       // [64][128]
    float* Red = Ws + 64 * 128;        // 2 x [8][129]
    __shared__ float sS[64], sH[64];
    int t = threadIdx.x;
    if (t < 64) { sS[t] = g_scale1[t]; sH[t] = g_shift1[t]; }
    for (int idx = t; idx < 64 * 128; idx += 128) {
        int c = idx >> 7, o = idx & 127;
        Ws[idx] = w[o * 64 + c];
    }
    __syncthreads();
    {
        int r = t;
        size_t gr = (size_t)blockIdx.x * 128 + r;
        const float4* src = (const float4*)(g_y1 + gr * 64);
        #pragma unroll 4
        for (int ch = 0; ch < 16; ch++) {
            float4 v = src[ch]; int c0 = ch * 4;
            XsT[(c0+0)*128 + r] = fmaxf(0.f, fmaf(v.x, sS[c0],   sH[c0]));
            XsT[(c0+1)*128 + r] = fmaxf(0.f, fmaf(v.y, sS[c0+1], sH[c0+1]));
            XsT[(c0+2)*128 + r] = fmaxf(0.f, fmaf(v.z, sS[c0+2], sH[c0+2]));
            XsT[(c0+3)*128 + r] = fmaxf(0.f, fmaf(v.w, sS[c0+3], sH[c0+3]));
        }
    }
    __syncthreads();
    int rg = t >> 4, cg = t & 15;
    ull acc[8][8];
    #pragma unroll
    for (int i = 0; i < 8; i++) {
        float bb = bias[cg*8+i];
        ull bp = pack2(bb, bb);
        #pragma unroll
        for (int p = 0; p < 8; p++) acc[p][i] = bp;
    }
    for (int c = 0; c < 64; c++) {
        const float4* ap = (const float4*)(XsT + c*128 + rg*16);
        float4 a0 = ap[0], a1 = ap[1], a2 = ap[2], a3 = ap[3];
        ull apair[8] = {pack2(a0.x,a0.y), pack2(a0.z,a0.w),
                        pack2(a1.x,a1.y), pack2(a1.z,a1.w),
                        pack2(a2.x,a2.y), pack2(a2.z,a2.w),
                        pack2(a3.x,a3.y), pack2(a3.z,a3.w)};
        const float4* wp = (const float4*)(Ws + c*128 + cg*8);
        float4 w0 = wp[0], w1 = wp[1];
        float wf[8] = {w0.x,w0.y,w0.z,w0.w,w1.x,w1.y,w1.z,w1.w};
        #pragma unroll
        for (int i = 0; i < 8; i++) {
            ull wd = pack2(wf[i], wf[i]);
            #pragma unroll
            for (int p = 0; p < 8; p++) fma2(acc[p][i], apair[p], wd);
        }
    }
    float s1[8], s2[8], mx[8], mn[8];
    #pragma unroll
    for (int i = 0; i < 8; i++) { s1[i]=0.f; s2[i]=0.f; mx[i]=-3.4e38f; mn[i]=3.4e38f; }
    #pragma unroll
    for (int p = 0; p < 8; p++) {
        #pragma unroll
        for (int i = 0; i < 8; i++) {
            float2 v = unpack2(acc[p][i]);
            s1[i] += v.x + v.y;
            s2[i] += v.x*v.x + v.y*v.y;
            mx[i] = fmaxf(mx[i], fmaxf(v.x, v.y));
            mn[i] = fminf(mn[i], fminf(v.x, v.y));
        }
    }
    #pragma unroll
    for (int i = 0; i < 8; i++) {
        int col = cg*8 + i;
        Red[rg*129 + col]        = s1[i];
        Red[1032 + rg*129 + col] = s2[i];
    }
    __syncthreads();
    {
        int col = t;
        float sa = 0.f, sb = 0.f;
        #pragma unroll
        for (int j = 0; j < 8; j++) { sa += Red[j*129 + col]; sb += Red[1032 + j*129 + col]; }
        g_part2[blockIdx.x*256 + col] = sa;
        g_part2[blockIdx.x*256 + 128 + col] = sb;
    }
    __syncthreads();
    #pragma unroll
    for (int i = 0; i < 8; i++) {
        int col = cg*8 + i;
        Red[rg*129 + col]        = mx[i];
        Red[1032 + rg*129 + col] = mn[i];
    }
    __syncthreads();
    {
        int col = t;
        #pragma unroll
        for (int g = 0; g < 4; g++) {
            size_t bs = (size_t)blockIdx.x * 4 + g;
            float m = fmaxf(Red[(2*g)*129 + col], Red[(2*g+1)*129 + col]);
            float n = fminf(Red[1032 + (2*g)*129 + col], Red[1032 + (2*g+1)*129 + col]);
            g_pmax[bs*128 + col] = m;
            g_pmin[bs*128 + col] = n;
        }
    }
}

// ------------- BN stats -------------
__global__ void __launch_bounds__(256) stats_kernel(int layer, int nblk, int C,
                             const float* __restrict__ gamma, const float* __restrict__ beta) {
    int c = blockIdx.x;
    int t = threadIdx.x;
    const float* part = (layer == 0) ? g_part0 : (layer == 1) ? g_part1 : g_part2;
    float s1 = 0.f, s2 = 0.f;
    for (int bk = t; bk < nblk; bk += 256) {
        s1 += part[(size_t)bk*2*C + c];
        s2 += part[(size_t)bk*2*C + C + c];
    }
    __shared__ float r1[256], r2[256];
    r1[t] = s1; r2[t] = s2;
    __syncthreads();
    for (int off = 128; off >= 1; off >>= 1) {
        if (t < off) { r1[t] += r1[t+off]; r2[t] += r2[t+off]; }
        __syncthreads();
    }
    if (t == 0) {
        const float n = 524288.f;
        float mean = r1[0] / n;
        float var = r2[0] / n - mean * mean;
        float sc = gamma[c] * rsqrtf(var + EPSF);
        float sf = beta[c] - mean * sc;
        if (layer == 0)      { g_scale0[c] = sc; g_shift0[c] = sf; }
        else if (layer == 1) { g_scale1[c] = sc; g_shift1[c] = sf; }
        else                 { g_scale2[c] = sc; g_shift2[c] = sf; }
    }
}

// ------------- pool epilogue -------------
__global__ void pool2_kernel(float* __restrict__ out, int pts_off) {
    int bs = blockIdx.x;
    int c = threadIdx.x;
    float sc = g_scale2[c], sf = g_shift2[c];
    float v = (sc >= 0.f) ? g_pmax[(size_t)bs*128 + c] : g_pmin[(size_t)bs*128 + c];
    float m = fmaxf(fmaf(v, sc, sf), 0.f);
    out[pts_off + (bs >> 10) * (128 * 1024) + c * 1024 + (bs & 1023)] = m;
}

extern "C" void kernel_launch(void* const* d_in, const int* in_sizes, int n_in,
                              void* d_out, int out_size) {
    const float* xyz    = (const float*)d_in[0];
    const float* points = (const float*)d_in[1];
    const float* w0 = (const float*)d_in[2];  const float* b0  = (const float*)d_in[3];
    const float* g0 = (const float*)d_in[4];  const float* be0 = (const float*)d_in[5];
    const float* w1 = (const float*)d_in[6];  const float* b1  = (const float*)d_in[7];
    const float* g1 = (const float*)d_in[8];  const float* be1 = (const float*)d_in[9];
    const float* w2 = (const float*)d_in[10]; const float* b2  = (const float*)d_in[11];
    const float* g2 = (const float*)d_in[12]; const float* be2 = (const float*)d_in[13];
    float* out = (float*)d_out;

    int npts = B_ * 128 * S_;
    int pts_off = out_size - npts;
    if (pts_off < 0) pts_off = 0;

    cudaFuncSetAttribute(fps_kernel,    cudaFuncAttributeMaxDynamicSharedMemorySize, FPS_SMEM);
    cudaFuncSetAttribute(knn_kernel,    cudaFuncAttributeMaxDynamicSharedMemorySize, KNN_SMEM);
    cudaFuncSetAttribute(gemmP_kernel,  cudaFuncAttributeMaxDynamicSharedMemorySize, LA_SMEM);
    cudaFuncSetAttribute(layer1_kernel, cudaFuncAttributeMaxDynamicSharedMemorySize, L1_SMEM);
    cudaFuncSetAttribute(layer2_kernel, cudaFuncAttributeMaxDynamicSharedMemorySize, L2_SMEM);

    fps_kernel<<<B_, 1024, FPS_SMEM>>>(xyz, out, pts_off > 0 ? 1 : 0);
    gemmP_kernel<<<256, 128, LA_SMEM>>>(points, w0, b0);
    knn_kernel<<<B_ * 128, 256, KNN_SMEM>>>(xyz);
    layer0b_kernel<<<16384, 256>>>(xyz, w0);
    stats_kernel<<<64, 256>>>(0, 16384, 64, g0, be0);
    layer1_kernel<<<2048, 128, L1_SMEM>>>(w1, b1);
    stats_kernel<<<64, 256>>>(1, 2048, 64, g1, be1);
    layer2_kernel<<<4096, 128, L2_SMEM>>>(w2, b2);
    stats_kernel<<<128, 256>>>(2, 4096, 128, g2, be2);
    pool2_kernel<<<B_ * S_, 128>>>(out, pts_off);
}

// round 13
// speedup vs baseline: 1.5261x; 1.1474x over previous
#include <cuda_runtime.h>
#include <cuda_bf16.h>
#include <cstdint>

#define FULLMASK 0xffffffffu
typedef unsigned long long ull;
namespace {
constexpr int B_ = 16, N_ = 4096, S_ = 1024, K_ = 32;
constexpr float EPSF = 1e-5f;
constexpr int FPS_SMEM = 3 * N_ * 4;
constexpr int KNN_SMEM = 4 * N_ * 4;
constexpr int LA_SMEM = (64 * 256 + 64 * 64) * 4;                 // 81920 (gemmP)
constexpr int L1_SMEM = (64 * 256 + 64 * 64 + 2 * 16 * 65) * 4;   // 90240
constexpr int L2M_SMEM = 4 * 128 * 72 * 2;                        // 73728 (Xh,Xl,Wh,Wl bf16)
}

// ------------- scratch -------------
__device__ int      g_fps[B_ * S_];
__device__ float    g_newxyz[B_ * S_ * 3];
__device__ float    g_d2[B_ * N_];
__device__ int      g_nn[B_ * S_ * K_];
__device__ float    g_P[B_ * N_ * 64];
__device__ float    g_y0[B_ * S_ * K_ * 64];
__device__ float    g_y1[B_ * S_ * K_ * 64];
__device__ float    g_pmax[B_ * S_ * 128];
__device__ float    g_pmin[B_ * S_ * 128];
__device__ float    g_part0[16384 * 128];
__device__ float    g_part1[2048 * 128];
__device__ float    g_part2[4096 * 256];
__device__ float    g_scale0[64], g_shift0[64];
__device__ float    g_scale1[64], g_shift1[64];
__device__ float    g_scale2[128], g_shift2[128];

// ------------- packed fp32x2 helpers (bit-exact) -------------
__device__ __forceinline__ ull pack2(float lo, float hi) {
    ull r;
    asm("mov.b64 %0, {%1, %2};" : "=l"(r) : "f"(lo), "f"(hi));
    return r;
}
__device__ __forceinline__ void fma2(ull& d, ull a, ull b) {
    asm("fma.rn.f32x2 %0, %1, %2, %0;" : "+l"(d) : "l"(a), "l"(b));
}
__device__ __forceinline__ ull add2(ull a, ull b) {
    ull r; asm("add.rn.f32x2 %0, %1, %2;" : "=l"(r) : "l"(a), "l"(b)); return r;
}
__device__ __forceinline__ ull mul2(ull a, ull b) {
    ull r; asm("mul.rn.f32x2 %0, %1, %2;" : "=l"(r) : "l"(a), "l"(b)); return r;
}
__device__ __forceinline__ float2 unpack2(ull v) {
    float lo, hi;
    asm("mov.b64 {%0, %1}, %2;" : "=f"(lo), "=f"(hi) : "l"(v));
    return make_float2(lo, hi);
}

// ------------- legacy tensor-core mma (sm_80+ baseline, OK on sm_103) --------
__device__ __forceinline__ void mma16816(float* c, const uint32_t* a, uint32_t b0, uint32_t b1) {
    asm volatile(
        "mma.sync.aligned.m16n8k16.row.col.f32.bf16.bf16.f32 "
        "{%0,%1,%2,%3}, {%4,%5,%6,%7}, {%8,%9}, {%0,%1,%2,%3};"
        : "+f"(c[0]), "+f"(c[1]), "+f"(c[2]), "+f"(c[3])
        : "r"(a[0]), "r"(a[1]), "r"(a[2]), "r"(a[3]), "r"(b0), "r"(b1));
}
__device__ __forceinline__ uint32_t bf16pack(float a0, float a1) {
    __nv_bfloat16 h0 = __float2bfloat16(a0);
    __nv_bfloat16 h1 = __float2bfloat16(a1);
    return ((uint32_t)__bfloat16_as_ushort(h1) << 16) | __bfloat16_as_ushort(h0);
}

// ------------- KNN helpers -------------
__device__ __forceinline__ void cmpswap(float& k, int& v, int j, bool dirAsc, int lane) {
    float ok = __shfl_xor_sync(FULLMASK, k, j);
    int   ov = __shfl_xor_sync(FULLMASK, v, j);
    bool takeOther = (((lane & j) == 0) == dirAsc) ? (ok < k) : (ok > k);
    if (takeOther) { k = ok; v = ov; }
}
__device__ __forceinline__ void bitonic_merge_asc(float& k, int& v, int lane) {
    #pragma unroll
    for (int j = 16; j > 0; j >>= 1) cmpswap(k, v, j, true, lane);
}
__device__ __forceinline__ void bitonic_sort_asc(float& k, int& v, int lane) {
    #pragma unroll
    for (int kk = 2; kk <= 16; kk <<= 1) {
        bool dir = ((lane & kk) == 0);
        #pragma unroll
        for (int j = kk >> 1; j > 0; j >>= 1) cmpswap(k, v, j, dir, lane);
    }
    bitonic_merge_asc(k, v, lane);
}

// ------------- FPS + fused prep tail -------------
__global__ void __launch_bounds__(1024) fps_kernel(const float* __restrict__ xyz,
                                                   float* __restrict__ out, int write_xyz) {
    int b = blockIdx.x;
    extern __shared__ float sh[];
    float* sx = sh; float* sy = sh + N_; float* sz = sh + 2 * N_;
    __shared__ unsigned swv[2][32];
    __shared__ unsigned swi[2][32];
    int t = threadIdx.x, w = t >> 5, lane = t & 31;
    const float* X = xyz + (size_t)b * N_ * 3;
    for (int i = t; i < N_; i += 1024) { sx[i] = X[3*i]; sy[i] = X[3*i+1]; sz[i] = X[3*i+2]; }
    __syncthreads();
    ull rxp[2], ryp[2], rzp[2];
    float dist[4];
    #pragma unroll
    for (int p = 0; p < 2; p++) {
        int i0 = t + (2*p) * 1024, i1 = t + (2*p+1) * 1024;
        rxp[p] = pack2(sx[i0], sx[i1]);
        ryp[p] = pack2(sy[i0], sy[i1]);
        rzp[p] = pack2(sz[i0], sz[i1]);
        dist[2*p] = 1e10f; dist[2*p+1] = 1e10f;
    }
    int far = 0;
    for (int it = 0; it < S_; ++it) {
        if (t == 0) g_fps[b * S_ + it] = far;
        float cx = sx[far], cy = sy[far], cz = sz[far];
        ull ncx = pack2(-cx, -cx), ncy = pack2(-cy, -cy), ncz = pack2(-cz, -cz);
        float bv = -1.0f; int bi = 0;
        #pragma unroll
        for (int p = 0; p < 2; p++) {
            ull dx = add2(rxp[p], ncx);
            ull dy = add2(ryp[p], ncy);
            ull dz = add2(rzp[p], ncz);
            ull s = add2(add2(mul2(dx,dx), mul2(dy,dy)), mul2(dz,dz));
            float2 d = unpack2(s);
            float dm0 = fminf(dist[2*p], d.x);   dist[2*p] = dm0;
            if (dm0 > bv) { bv = dm0; bi = t + (2*p) * 1024; }
            float dm1 = fminf(dist[2*p+1], d.y); dist[2*p+1] = dm1;
            if (dm1 > bv) { bv = dm1; bi = t + (2*p+1) * 1024; }
        }
        unsigned db = __float_as_uint(bv);
        unsigned mx = __reduce_max_sync(FULLMASK, db);
        unsigned cand = (db == mx) ? (unsigned)bi : 0xffffffffu;
        unsigned mi = __reduce_min_sync(FULLMASK, cand);
        int buf = it & 1;
        if (lane == 0) { swv[buf][w] = mx; swi[buf][w] = mi; }
        __syncthreads();
        unsigned v2 = swv[buf][lane];
        unsigned i2 = swi[buf][lane];
        unsigned mx2 = __reduce_max_sync(FULLMASK, v2);
        unsigned c2 = (v2 == mx2) ? i2 : 0xffffffffu;
        far = (int)__reduce_min_sync(FULLMASK, c2);
    }
    __syncthreads();
    #pragma unroll
    for (int r = 0; r < 4; r++) {
        int i = t + r * 1024;
        float x = sx[i], y = sy[i], z = sz[i];
        g_d2[b * N_ + i] = __fadd_rn(__fadd_rn(__fmul_rn(x,x), __fmul_rn(y,y)), __fmul_rn(z,z));
    }
    {
        int i = t;
        int n = g_fps[b * S_ + i];
        float px = sx[n], py = sy[n], pz = sz[n];
        int gi = b * S_ + i;
        g_newxyz[3*gi] = px; g_newxyz[3*gi+1] = py; g_newxyz[3*gi+2] = pz;
        if (write_xyz) { out[3*gi] = px; out[3*gi+1] = py; out[3*gi+2] = pz; }
    }
}

// ------------- KNN -------------
__global__ void __launch_bounds__(256) knn_kernel(const float* __restrict__ xyz) {
    extern __shared__ float sh[];
    float* sx = sh; float* sy = sh + N_; float* sz = sh + 2*N_; float* sd = sh + 3*N_;
    int t = threadIdx.x;
    int b = blockIdx.x >> 7;
    int s0 = (blockIdx.x & 127) * 8;
    const float* X = xyz + (size_t)b * N_ * 3;
    for (int i = t; i < N_; i += 256) {
        sx[i] = X[3*i]; sy[i] = X[3*i+1]; sz[i] = X[3*i+2];
        sd[i] = g_d2[b * N_ + i];
    }
    __syncthreads();
    int w = t >> 5, lane = t & 31;
    int q = b * S_ + s0 + w;
    float qx = g_newxyz[3*q], qy = g_newxyz[3*q+1], qz = g_newxyz[3*q+2];
    float q2 = __fadd_rn(__fadd_rn(__fmul_rn(qx,qx), __fmul_rn(qy,qy)), __fmul_rn(qz,qz));
    float key = 3.0e38f; int kid = 0; float curmax = 3.0e38f;
    for (int c = 0; c < N_ / 32; c++) {
        int p = c * 32 + lane;
        float dot = __fadd_rn(__fadd_rn(__fmul_rn(qx, sx[p]),
                                        __fmul_rn(qy, sy[p])),
                              __fmul_rn(qz, sz[p]));
        float d = __fsub_rn(__fadd_rn(q2, sd[p]), __fmul_rn(2.0f, dot));
        unsigned m = __ballot_sync(FULLMASK, d < curmax);
        if (!m) continue;
        if (__popc(m) <= 6) {
            while (m) {
                int src = __ffs(m) - 1;
                m &= m - 1;
                float v  = __shfl_sync(FULLMASK, d, src);
                int   vi = __shfl_sync(FULLMASK, p, src);
                if (v < curmax) {
                    unsigned lt = __ballot_sync(FULLMASK, key < v);
                    int pos = __popc(lt);
                    float ku = __shfl_up_sync(FULLMASK, key, 1);
                    int   iu = __shfl_up_sync(FULLMASK, kid, 1);
                    if (lane == pos)      { key = v;  kid = vi; }
                    else if (lane > pos)  { key = ku; kid = iu; }
                    curmax = __shfl_sync(FULLMASK, key, 31);
                }
            }
        } else {
            float nk = d; int ni = p;
            bitonic_sort_asc(nk, ni, lane);
            float rk = __shfl_sync(FULLMASK, nk, 31 - lane);
            int   ri = __shfl_sync(FULLMASK, ni, 31 - lane);
            if (rk < key) { key = rk; kid = ri; }
            bitonic_merge_asc(key, kid, lane);
            curmax = __shfl_sync(FULLMASK, key, 31);
        }
    }
    g_nn[q * K_ + lane] = kid;
}

// ------------- kernel A: P = W0[:,3:]·points + b0 -------------
__global__ void __launch_bounds__(128, 1) gemmP_kernel(const float* __restrict__ points,
                                                       const float* __restrict__ w,
                                                       const float* __restrict__ bias) {
    extern __shared__ float sh[];
    float* XsT = sh;
    float* Ws  = XsT + 64 * 256;
    int t = threadIdx.x;
    for (int idx = t; idx < 64 * 64; idx += 128) {
        int c = idx >> 6, o = idx & 63;
        Ws[idx] = w[o * 67 + 3 + c];
    }
    #pragma unroll
    for (int rr = 0; rr < 2; rr++) {
        int r = t + rr * 128;
        size_t gr = (size_t)blockIdx.x * 256 + r;
        const float4* src = (const float4*)(points + gr * 64);
        #pragma unroll 4
        for (int ch = 0; ch < 16; ch++) {
            float4 v = src[ch];
            XsT[(ch*4+0)*256 + r] = v.x;
            XsT[(ch*4+1)*256 + r] = v.y;
            XsT[(ch*4+2)*256 + r] = v.z;
            XsT[(ch*4+3)*256 + r] = v.w;
        }
    }
    __syncthreads();
    int rg = t >> 3, cg = t & 7;
    ull acc[8][8];
    #pragma unroll
    for (int i = 0; i < 8; i++) {
        float bb = bias[cg*8+i];
        ull bp = pack2(bb, bb);
        #pragma unroll
        for (int p = 0; p < 8; p++) acc[p][i] = bp;
    }
    for (int c = 0; c < 64; c++) {
        const float4* ap = (const float4*)(XsT + c*256 + rg*16);
        float4 a0 = ap[0], a1 = ap[1], a2 = ap[2], a3 = ap[3];
        ull apair[8] = {pack2(a0.x,a0.y), pack2(a0.z,a0.w),
                        pack2(a1.x,a1.y), pack2(a1.z,a1.w),
                        pack2(a2.x,a2.y), pack2(a2.z,a2.w),
                        pack2(a3.x,a3.y), pack2(a3.z,a3.w)};
        const float4* wp = (const float4*)(Ws + c*64 + cg*8);
        float4 w0 = wp[0], w1 = wp[1];
        float wf[8] = {w0.x,w0.y,w0.z,w0.w,w1.x,w1.y,w1.z,w1.w};
        #pragma unroll
        for (int i = 0; i < 8; i++) {
            ull wd = pack2(wf[i], wf[i]);
            #pragma unroll
            for (int p = 0; p < 8; p++) fma2(acc[p][i], apair[p], wd);
        }
    }
    #pragma unroll
    for (int p = 0; p < 8; p++) {
        float lo[8], hi[8];
        #pragma unroll
        for (int i = 0; i < 8; i++) { float2 v = unpack2(acc[p][i]); lo[i] = v.x; hi[i] = v.y; }
        size_t r0 = (size_t)blockIdx.x * 256 + rg*16 + 2*p;
        float4* d0 = (float4*)(g_P + r0 * 64 + cg*8);
        d0[0] = make_float4(lo[0],lo[1],lo[2],lo[3]);
        d0[1] = make_float4(lo[4],lo[5],lo[6],lo[7]);
        float4* d1 = (float4*)(g_P + (r0+1) * 64 + cg*8);
        d1[0] = make_float4(hi[0],hi[1],hi[2],hi[3]);
        d1[1] = make_float4(hi[4],hi[5],hi[6],hi[7]);
    }
}

// ------------- kernel B: y0 = P[n] + xyz_diff·W0[:,0:3], + BN0 stats -----------
__global__ void __launch_bounds__(256) layer0b_kernel(const float* __restrict__ xyz,
                                                      const float* __restrict__ w) {
    __shared__ float sw[3 * 64];
    __shared__ float Red[2 * 2080];
    int t = threadIdx.x;
    if (t < 192) {
        int k = t >> 6, o = t & 63;
        sw[k * 64 + o] = w[o * 67 + k];
    }
    __syncthreads();
    int rg = t >> 3, cg = t & 7;
    int gr = blockIdx.x * 32 + rg;
    int q = gr >> 5, b = gr >> 15;
    int n = g_nn[gr];
    const float* pp = xyz + ((size_t)b * N_ + n) * 3;
    float dx = __fadd_rn(pp[0], -g_newxyz[3*q]);
    float dy = __fadd_rn(pp[1], -g_newxyz[3*q+1]);
    float dz = __fadd_rn(pp[2], -g_newxyz[3*q+2]);
    const float4* Pp = (const float4*)(g_P + ((size_t)b * N_ + n) * 64) + cg * 2;
    float4 p0 = Pp[0], p1 = Pp[1];
    float y[8] = {p0.x,p0.y,p0.z,p0.w,p1.x,p1.y,p1.z,p1.w};
    #pragma unroll
    for (int i = 0; i < 8; i++) {
        int o = cg*8 + i;
        y[i] = fmaf(dz, sw[128+o], fmaf(dy, sw[64+o], fmaf(dx, sw[o], y[i])));
    }
    float4* dst = (float4*)(g_y0 + (size_t)gr * 64 + cg * 8);
    dst[0] = make_float4(y[0],y[1],y[2],y[3]);
    dst[1] = make_float4(y[4],y[5],y[6],y[7]);
    #pragma unroll
    for (int i = 0; i < 8; i++) Red[rg*65 + cg*8 + i] = y[i];
    __syncthreads();
    if (t < 64) {
        float s = 0.f;
        #pragma unroll 8
        for (int j = 0; j < 32; j++) s += Red[j*65 + t];
        g_part0[(size_t)blockIdx.x*128 + t] = s;
    }
    __syncthreads();
    #pragma unroll
    for (int i = 0; i < 8; i++) Red[rg*65 + cg*8 + i] = y[i]*y[i];
    __syncthreads();
    if (t < 64) {
        float s = 0.f;
        #pragma unroll 8
        for (int j = 0; j < 32; j++) s += Red[j*65 + t];
        g_part0[(size_t)blockIdx.x*128 + 64 + t] = s;
    }
}

// ------------- layer 1: BN0+ReLU fused gather, GEMM 64->64 (scalar FFMA2) -----
__global__ void __launch_bounds__(128, 1) layer1_kernel(const float* __restrict__ w,
                                                        const float* __restrict__ bias) {
    extern __shared__ float sh[];
    float* XsT = sh;
    float* Ws  = XsT + 64 * 256;
    float* Red = Ws + 64 * 64;
    __shared__ float sS[64], sH[64];
    int t = threadIdx.x;
    if (t < 64) { sS[t] = g_scale0[t]; sH[t] = g_shift0[t]; }
    for (int idx = t; idx < 64 * 64; idx += 128) {
        int c = idx >> 6, o = idx & 63;
        Ws[idx] = w[o * 64 + c];
    }
    __syncthreads();
    #pragma unroll
    for (int rr = 0; rr < 2; rr++) {
        int r = t + rr * 128;
        size_t gr = (size_t)blockIdx.x * 256 + r;
        const float4* src = (const float4*)(g_y0 + gr * 64);
        #pragma unroll 4
        for (int ch = 0; ch < 16; ch++) {
            float4 v = src[ch]; int c0 = ch * 4;
            XsT[(c0+0)*256 + r] = fmaxf(0.f, fmaf(v.x, sS[c0],   sH[c0]));
            XsT[(c0+1)*256 + r] = fmaxf(0.f, fmaf(v.y, sS[c0+1], sH[c0+1]));
            XsT[(c0+2)*256 + r] = fmaxf(0.f, fmaf(v.z, sS[c0+2], sH[c0+2]));
            XsT[(c0+3)*256 + r] = fmaxf(0.f, fmaf(v.w, sS[c0+3], sH[c0+3]));
        }
    }
    __syncthreads();
    int rg = t >> 3, cg = t & 7;
    ull acc[8][8];
    #pragma unroll
    for (int i = 0; i < 8; i++) {
        float bb = bias[cg*8+i];
        ull bp = pack2(bb, bb);
        #pragma unroll
        for (int p = 0; p < 8; p++) acc[p][i] = bp;
    }
    for (int c = 0; c < 64; c++) {
        const float4* ap = (const float4*)(XsT + c*256 + rg*16);
        float4 a0 = ap[0], a1 = ap[1], a2 = ap[2], a3 = ap[3];
        ull apair[8] = {pack2(a0.x,a0.y), pack2(a0.z,a0.w),
                        pack2(a1.x,a1.y), pack2(a1.z,a1.w),
                        pack2(a2.x,a2.y), pack2(a2.z,a2.w),
                        pack2(a3.x,a3.y), pack2(a3.z,a3.w)};
        const float4* wp = (const float4*)(Ws + c*64 + cg*8);
        float4 w0 = wp[0], w1 = wp[1];
        float wf[8] = {w0.x,w0.y,w0.z,w0.w,w1.x,w1.y,w1.z,w1.w};
        #pragma unroll
        for (int i = 0; i < 8; i++) {
            ull wd = pack2(wf[i], wf[i]);
            #pragma unroll
            for (int p = 0; p < 8; p++) fma2(acc[p][i], apair[p], wd);
        }
    }
    float s1[8], s2[8];
    #pragma unroll
    for (int i = 0; i < 8; i++) { s1[i] = 0.f; s2[i] = 0.f; }
    #pragma unroll
    for (int p = 0; p < 8; p++) {
        float lo[8], hi[8];
        #pragma unroll
        for (int i = 0; i < 8; i++) { float2 v = unpack2(acc[p][i]); lo[i] = v.x; hi[i] = v.y; }
        size_t r0 = (size_t)blockIdx.x * 256 + rg*16 + 2*p;
        float4* d0 = (float4*)(g_y1 + r0 * 64 + cg*8);
        d0[0] = make_float4(lo[0],lo[1],lo[2],lo[3]);
        d0[1] = make_float4(lo[4],lo[5],lo[6],lo[7]);
        float4* d1 = (float4*)(g_y1 + (r0+1) * 64 + cg*8);
        d1[0] = make_float4(hi[0],hi[1],hi[2],hi[3]);
        d1[1] = make_float4(hi[4],hi[5],hi[6],hi[7]);
        #pragma unroll
        for (int i = 0; i < 8; i++) { s1[i] += lo[i]+hi[i]; s2[i] += lo[i]*lo[i]+hi[i]*hi[i]; }
    }
    #pragma unroll
    for (int i = 0; i < 8; i++) {
        int col = cg*8 + i;
        Red[rg*65 + col]        = s1[i];
        Red[1040 + rg*65 + col] = s2[i];
    }
    __syncthreads();
    if (t < 64) {
        float s = 0.f;
        #pragma unroll 4
        for (int j = 0; j < 16; j++) s += Red[j*65 + t];
        g_part1[blockIdx.x*128 + t] = s;
    } else {
        int col = t - 64; float s = 0.f;
        #pragma unroll 4
        for (int j = 0; j < 16; j++) s += Red[1040 + j*65 + col];
        g_part1[blockIdx.x*128 + 64 + col] = s;
    }
}

// ------------- layer 2: bf16-split mma.sync (legacy HMMA), fused pool ---------
// D[row][ch] = BN1relu(y1)[row][0:64] · W2[ch][0:64]^T  via Ah·Bh + Ah·Bl + Al·Bh
// block: 128 rows x 128 ch; warp w: rows 16w..16w+15.
__global__ void __launch_bounds__(256, 1) layer2_mma_kernel(const float* __restrict__ w2,
                                                            const float* __restrict__ b2) {
    extern __shared__ char sm[];
    __nv_bfloat16* Xh = (__nv_bfloat16*)sm;        // [128 rows][72]
    __nv_bfloat16* Xl = Xh + 128 * 72;
    __nv_bfloat16* Wh = Xl + 128 * 72;             // [128 ch][72]
    __nv_bfloat16* Wl = Wh + 128 * 72;
    float* Dst = (float*)sm;                       // reused post-MMA: [128][132]
    __shared__ float sS[64], sH[64], sB[128], sr1[128], sr2[128];
    int t = threadIdx.x, w = t >> 5, lane = t & 31;
    int g = lane >> 2, tq = lane & 3;

    if (t < 64) { sS[t] = g_scale1[t]; sH[t] = g_shift1[t]; }
    if (t < 128) sB[t] = b2[t];
    // W2 split: ch = t&127, k half = (t>>7)*32
    {
        int ch = t & 127, k0 = (t >> 7) * 32;
        const float4* src = (const float4*)(w2 + (size_t)ch * 64 + k0);
        #pragma unroll
        for (int j = 0; j < 8; j++) {
            float4 v = src[j];
            float vv[4] = {v.x, v.y, v.z, v.w};
            #pragma unroll
            for (int i = 0; i < 4; i++) {
                float a = vv[i];
                __nv_bfloat16 h = __float2bfloat16(a);
                __nv_bfloat16 l = __float2bfloat16(__fsub_rn(a, __bfloat162float(h)));
                Wh[ch * 72 + k0 + 4*j + i] = h;
                Wl[ch * 72 + k0 + 4*j + i] = l;
            }
        }
    }
    __syncthreads();   // sS/sH ready
    // X split with BN1+ReLU: row = t&127, k half = (t>>7)*32
    {
        int r = t & 127, k0 = (t >> 7) * 32;
        size_t gr = (size_t)blockIdx.x * 128 + r;
        const float4* src = (const float4*)(g_y1 + gr * 64 + k0);
        #pragma unroll
        for (int j = 0; j < 8; j++) {
            float4 v = src[j];
            float vv[4] = {v.x, v.y, v.z, v.w};
            #pragma unroll
            for (int i = 0; i < 4; i++) {
                int c = k0 + 4*j + i;
                float a = fmaxf(0.f, fmaf(vv[i], sS[c], sH[c]));
                __nv_bfloat16 h = __float2bfloat16(a);
                __nv_bfloat16 l = __float2bfloat16(__fsub_rn(a, __bfloat162float(h)));
                Xh[r * 72 + c] = h;
                Xl[r * 72 + c] = l;
            }
        }
    }
    __syncthreads();

    // A fragments register-resident (4 k-steps of 16)
    int R0 = w * 16;
    uint32_t ah[4][4], al[4][4];
    #pragma unroll
    for (int kk = 0; kk < 4; kk++) {
        int kb = kk * 16 + 2 * tq;
        ah[kk][0] = *(const uint32_t*)&Xh[(R0 + g)     * 72 + kb];
        ah[kk][1] = *(const uint32_t*)&Xh[(R0 + g + 8) * 72 + kb];
        ah[kk][2] = *(const uint32_t*)&Xh[(R0 + g)     * 72 + kb + 8];
        ah[kk][3] = *(const uint32_t*)&Xh[(R0 + g + 8) * 72 + kb + 8];
        al[kk][0] = *(const uint32_t*)&Xl[(R0 + g)     * 72 + kb];
        al[kk][1] = *(const uint32_t*)&Xl[(R0 + g + 8) * 72 + kb];
        al[kk][2] = *(const uint32_t*)&Xl[(R0 + g)     * 72 + kb + 8];
        al[kk][3] = *(const uint32_t*)&Xl[(R0 + g + 8) * 72 + kb + 8];
    }

    float c[16][4];
    #pragma unroll
    for (int cg = 0; cg < 16; cg++)
        #pragma unroll
        for (int i = 0; i < 4; i++) c[cg][i] = 0.f;

    #pragma unroll
    for (int cg = 0; cg < 16; cg++) {
        int chb = cg * 8 + g;
        #pragma unroll
        for (int kk = 0; kk < 4; kk++) {
            int kb = kk * 16 + 2 * tq;
            uint32_t bh0 = *(const uint32_t*)&Wh[chb * 72 + kb];
            uint32_t bh1 = *(const uint32_t*)&Wh[chb * 72 + kb + 8];
            uint32_t bl0 = *(const uint32_t*)&Wl[chb * 72 + kb];
            uint32_t bl1 = *(const uint32_t*)&Wl[chb * 72 + kb + 8];
            mma16816(c[cg], ah[kk], bh0, bh1);
            mma16816(c[cg], ah[kk], bl0, bl1);
            mma16816(c[cg], al[kk], bh0, bh1);
        }
    }
    __syncthreads();   // tiles no longer needed; reuse smem for D staging

    #pragma unroll
    for (int cg = 0; cg < 16; cg++) {
        int c0i = cg * 8 + 2 * tq;
        int r0 = R0 + g, r1 = r0 + 8;
        *(float2*)&Dst[r0 * 132 + c0i] = make_float2(c[cg][0], c[cg][1]);
        *(float2*)&Dst[r1 * 132 + c0i] = make_float2(c[cg][2], c[cg][3]);
    }
    __syncthreads();

    // epilogue: bias + stats + per-32-row-group max/min
    {
        int col = t & 127, half = t >> 7;
        float bb = sB[col];
        float s1 = 0.f, s2 = 0.f;
        #pragma unroll
        for (int grp = 0; grp < 2; grp++) {
            int rb = half * 64 + grp * 32;
            float mx = -3.4e38f, mn = 3.4e38f;
            #pragma unroll 8
            for (int r = 0; r < 32; r++) {
                float v = Dst[(rb + r) * 132 + col] + bb;
                s1 += v;
                s2 = fmaf(v, v, s2);
                mx = fmaxf(mx, v);
                mn = fminf(mn, v);
            }
            size_t bs = (size_t)blockIdx.x * 4 + half * 2 + grp;
            g_pmax[bs * 128 + col] = mx;
            g_pmin[bs * 128 + col] = mn;
        }
        if (half == 0) { sr1[col] = s1; sr2[col] = s2; }
        __syncthreads();
        if (half == 1) {
            g_part2[(size_t)blockIdx.x * 256 + col]       = sr1[col] + s1;
            g_part2[(size_t)blockIdx.x * 256 + 128 + col] = sr2[col] + s2;
        }
    }
}

// ------------- BN stats -------------
__global__ void __launch_bounds__(256) stats_kernel(int layer, int nblk, int C,
                             const float* __restrict__ gamma, const float* __restrict__ beta) {
    int c = blockIdx.x;
    int t = threadIdx.x;
    const float* part = (layer == 0) ? g_part0 : (layer == 1) ? g_part1 : g_part2;
    float s1 = 0.f, s2 = 0.f;
    for (int bk = t; bk < nblk; bk += 256) {
        s1 += part[(size_t)bk*2*C + c];
        s2 += part[(size_t)bk*2*C + C + c];
    }
    __shared__ float r1[256], r2[256];
    r1[t] = s1; r2[t] = s2;
    __syncthreads();
    for (int off = 128; off >= 1; off >>= 1) {
        if (t < off) { r1[t] += r1[t+off]; r2[t] += r2[t+off]; }
        __syncthreads();
    }
    if (t == 0) {
        const float n = 524288.f;
        float mean = r1[0] / n;
        float var = r2[0] / n - mean * mean;
        float sc = gamma[c] * rsqrtf(var + EPSF);
        float sf = beta[c] - mean * sc;
        if (layer == 0)      { g_scale0[c] = sc; g_shift0[c] = sf; }
        else if (layer == 1) { g_scale1[c] = sc; g_shift1[c] = sf; }
        else                 { g_scale2[c] = sc; g_shift2[c] = sf; }
    }
}

// ------------- pool epilogue -------------
__global__ void pool2_kernel(float* __restrict__ out, int pts_off) {
    int bs = blockIdx.x;
    int c = threadIdx.x;
    float sc = g_scale2[c], sf = g_shift2[c];
    float v = (sc >= 0.f) ? g_pmax[(size_t)bs*128 + c] : g_pmin[(size_t)bs*128 + c];
    float m = fmaxf(fmaf(v, sc, sf), 0.f);
    out[pts_off + (bs >> 10) * (128 * 1024) + c * 1024 + (bs & 1023)] = m;
}

extern "C" void kernel_launch(void* const* d_in, const int* in_sizes, int n_in,
                              void* d_out, int out_size) {
    const float* xyz    = (const float*)d_in[0];
    const float* points = (const float*)d_in[1];
    const float* w0 = (const float*)d_in[2];  const float* b0  = (const float*)d_in[3];
    const float* g0 = (const float*)d_in[4];  const float* be0 = (const float*)d_in[5];
    const float* w1 = (const float*)d_in[6];  const float* b1  = (const float*)d_in[7];
    const float* g1 = (const float*)d_in[8];  const float* be1 = (const float*)d_in[9];
    const float* w2 = (const float*)d_in[10]; const float* b2  = (const float*)d_in[11];
    const float* g2 = (const float*)d_in[12]; const float* be2 = (const float*)d_in[13];
    float* out = (float*)d_out;

    int npts = B_ * 128 * S_;
    int pts_off = out_size - npts;
    if (pts_off < 0) pts_off = 0;

    cudaFuncSetAttribute(fps_kernel,       cudaFuncAttributeMaxDynamicSharedMemorySize, FPS_SMEM);
    cudaFuncSetAttribute(knn_kernel,       cudaFuncAttributeMaxDynamicSharedMemorySize, KNN_SMEM);
    cudaFuncSetAttribute(gemmP_kernel,     cudaFuncAttributeMaxDynamicSharedMemorySize, LA_SMEM);
    cudaFuncSetAttribute(layer1_kernel,    cudaFuncAttributeMaxDynamicSharedMemorySize, L1_SMEM);
    cudaFuncSetAttribute(layer2_mma_kernel,cudaFuncAttributeMaxDynamicSharedMemorySize, L2M_SMEM);

    fps_kernel<<<B_, 1024, FPS_SMEM>>>(xyz, out, pts_off > 0 ? 1 : 0);
    gemmP_kernel<<<256, 128, LA_SMEM>>>(points, w0, b0);
    knn_kernel<<<B_ * 128, 256, KNN_SMEM>>>(xyz);
    layer0b_kernel<<<16384, 256>>>(xyz, w0);
    stats_kernel<<<64, 256>>>(0, 16384, 64, g0, be0);
    layer1_kernel<<<2048, 128, L1_SMEM>>>(w1, b1);
    stats_kernel<<<64, 256>>>(1, 2048, 64, g1, be1);
    layer2_mma_kernel<<<4096, 256, L2M_SMEM>>>(w2, b2);
    stats_kernel<<<128, 256>>>(2, 4096, 128, g2, be2);
    pool2_kernel<<<B_ * S_, 128>>>(out, pts_off);
}

// round 14
// speedup vs baseline: 1.6282x; 1.0669x over previous
#include <cuda_runtime.h>
#include <cuda_bf16.h>
#include <cstdint>

#define FULLMASK 0xffffffffu
typedef unsigned long long ull;
namespace {
constexpr int B_ = 16, N_ = 4096, S_ = 1024, K_ = 32;
constexpr float EPSF = 1e-5f;
constexpr int FPS_SMEM = 3 * N_ * 4;
constexpr int KNN_SMEM = 4 * N_ * 4;
constexpr int LA_SMEM = (64 * 256 + 64 * 64) * 4;                 // 81920 (gemmP)
constexpr int L1M_SMEM = (128 + 64) * 72 * 2 * 2;                 // 55296 (Xh,Xl,Wh,Wl bf16)
constexpr int L2M_SMEM = 4 * 128 * 72 * 2;                        // 73728
}

// ------------- scratch -------------
__device__ int      g_fps[B_ * S_];
__device__ float    g_newxyz[B_ * S_ * 3];
__device__ float    g_d2[B_ * N_];
__device__ int      g_nn[B_ * S_ * K_];
__device__ float    g_P[B_ * N_ * 64];
__device__ float    g_y0[B_ * S_ * K_ * 64];
__device__ float    g_y1[B_ * S_ * K_ * 64];
__device__ float    g_pmax[B_ * S_ * 128];
__device__ float    g_pmin[B_ * S_ * 128];
__device__ float    g_part0[16384 * 128];
__device__ float    g_part1[4096 * 128];
__device__ float    g_part2[4096 * 256];
__device__ float    g_scale0[64], g_shift0[64];
__device__ float    g_scale1[64], g_shift1[64];
__device__ float    g_scale2[128], g_shift2[128];

// ------------- packed fp32x2 helpers (bit-exact) -------------
__device__ __forceinline__ ull pack2(float lo, float hi) {
    ull r;
    asm("mov.b64 %0, {%1, %2};" : "=l"(r) : "f"(lo), "f"(hi));
    return r;
}
__device__ __forceinline__ void fma2(ull& d, ull a, ull b) {
    asm("fma.rn.f32x2 %0, %1, %2, %0;" : "+l"(d) : "l"(a), "l"(b));
}
__device__ __forceinline__ ull add2(ull a, ull b) {
    ull r; asm("add.rn.f32x2 %0, %1, %2;" : "=l"(r) : "l"(a), "l"(b)); return r;
}
__device__ __forceinline__ ull mul2(ull a, ull b) {
    ull r; asm("mul.rn.f32x2 %0, %1, %2;" : "=l"(r) : "l"(a), "l"(b)); return r;
}
__device__ __forceinline__ float2 unpack2(ull v) {
    float lo, hi;
    asm("mov.b64 {%0, %1}, %2;" : "=f"(lo), "=f"(hi) : "l"(v));
    return make_float2(lo, hi);
}

// ------------- legacy tensor-core mma (sm_80+ baseline) -------------
__device__ __forceinline__ void mma16816(float* c, const uint32_t* a, uint32_t b0, uint32_t b1) {
    asm volatile(
        "mma.sync.aligned.m16n8k16.row.col.f32.bf16.bf16.f32 "
        "{%0,%1,%2,%3}, {%4,%5,%6,%7}, {%8,%9}, {%0,%1,%2,%3};"
        : "+f"(c[0]), "+f"(c[1]), "+f"(c[2]), "+f"(c[3])
        : "r"(a[0]), "r"(a[1]), "r"(a[2]), "r"(a[3]), "r"(b0), "r"(b1));
}

// ------------- KNN helpers -------------
__device__ __forceinline__ void cmpswap(float& k, int& v, int j, bool dirAsc, int lane) {
    float ok = __shfl_xor_sync(FULLMASK, k, j);
    int   ov = __shfl_xor_sync(FULLMASK, v, j);
    bool takeOther = (((lane & j) == 0) == dirAsc) ? (ok < k) : (ok > k);
    if (takeOther) { k = ok; v = ov; }
}
__device__ __forceinline__ void bitonic_merge_asc(float& k, int& v, int lane) {
    #pragma unroll
    for (int j = 16; j > 0; j >>= 1) cmpswap(k, v, j, true, lane);
}
__device__ __forceinline__ void bitonic_sort_asc(float& k, int& v, int lane) {
    #pragma unroll
    for (int kk = 2; kk <= 16; kk <<= 1) {
        bool dir = ((lane & kk) == 0);
        #pragma unroll
        for (int j = kk >> 1; j > 0; j >>= 1) cmpswap(k, v, j, dir, lane);
    }
    bitonic_merge_asc(k, v, lane);
}

// ------------- FPS + fused prep tail -------------
__global__ void __launch_bounds__(1024) fps_kernel(const float* __restrict__ xyz,
                                                   float* __restrict__ out, int write_xyz) {
    int b = blockIdx.x;
    extern __shared__ float sh[];
    float* sx = sh; float* sy = sh + N_; float* sz = sh + 2 * N_;
    __shared__ unsigned swv[2][32];
    __shared__ unsigned swi[2][32];
    int t = threadIdx.x, w = t >> 5, lane = t & 31;
    const float* X = xyz + (size_t)b * N_ * 3;
    for (int i = t; i < N_; i += 1024) { sx[i] = X[3*i]; sy[i] = X[3*i+1]; sz[i] = X[3*i+2]; }
    __syncthreads();
    ull rxp[2], ryp[2], rzp[2];
    float dist[4];
    #pragma unroll
    for (int p = 0; p < 2; p++) {
        int i0 = t + (2*p) * 1024, i1 = t + (2*p+1) * 1024;
        rxp[p] = pack2(sx[i0], sx[i1]);
        ryp[p] = pack2(sy[i0], sy[i1]);
        rzp[p] = pack2(sz[i0], sz[i1]);
        dist[2*p] = 1e10f; dist[2*p+1] = 1e10f;
    }
    int far = 0;
    for (int it = 0; it < S_; ++it) {
        if (t == 0) g_fps[b * S_ + it] = far;
        float cx = sx[far], cy = sy[far], cz = sz[far];
        ull ncx = pack2(-cx, -cx), ncy = pack2(-cy, -cy), ncz = pack2(-cz, -cz);
        float bv = -1.0f; int bi = 0;
        #pragma unroll
        for (int p = 0; p < 2; p++) {
            ull dx = add2(rxp[p], ncx);
            ull dy = add2(ryp[p], ncy);
            ull dz = add2(rzp[p], ncz);
            ull s = add2(add2(mul2(dx,dx), mul2(dy,dy)), mul2(dz,dz));
            float2 d = unpack2(s);
            float dm0 = fminf(dist[2*p], d.x);   dist[2*p] = dm0;
            if (dm0 > bv) { bv = dm0; bi = t + (2*p) * 1024; }
            float dm1 = fminf(dist[2*p+1], d.y); dist[2*p+1] = dm1;
            if (dm1 > bv) { bv = dm1; bi = t + (2*p+1) * 1024; }
        }
        unsigned db = __float_as_uint(bv);
        unsigned mx = __reduce_max_sync(FULLMASK, db);
        unsigned cand = (db == mx) ? (unsigned)bi : 0xffffffffu;
        unsigned mi = __reduce_min_sync(FULLMASK, cand);
        int buf = it & 1;
        if (lane == 0) { swv[buf][w] = mx; swi[buf][w] = mi; }
        __syncthreads();
        unsigned v2 = swv[buf][lane];
        unsigned i2 = swi[buf][lane];
        unsigned mx2 = __reduce_max_sync(FULLMASK, v2);
        unsigned c2 = (v2 == mx2) ? i2 : 0xffffffffu;
        far = (int)__reduce_min_sync(FULLMASK, c2);
    }
    __syncthreads();
    #pragma unroll
    for (int r = 0; r < 4; r++) {
        int i = t + r * 1024;
        float x = sx[i], y = sy[i], z = sz[i];
        g_d2[b * N_ + i] = __fadd_rn(__fadd_rn(__fmul_rn(x,x), __fmul_rn(y,y)), __fmul_rn(z,z));
    }
    {
        int i = t;
        int n = g_fps[b * S_ + i];
        float px = sx[n], py = sy[n], pz = sz[n];
        int gi = b * S_ + i;
        g_newxyz[3*gi] = px; g_newxyz[3*gi+1] = py; g_newxyz[3*gi+2] = pz;
        if (write_xyz) { out[3*gi] = px; out[3*gi+1] = py; out[3*gi+2] = pz; }
    }
}

// ------------- KNN -------------
__global__ void __launch_bounds__(256) knn_kernel(const float* __restrict__ xyz) {
    extern __shared__ float sh[];
    float* sx = sh; float* sy = sh + N_; float* sz = sh + 2*N_; float* sd = sh + 3*N_;
    int t = threadIdx.x;
    int b = blockIdx.x >> 7;
    int s0 = (blockIdx.x & 127) * 8;
    const float* X = xyz + (size_t)b * N_ * 3;
    for (int i = t; i < N_; i += 256) {
        sx[i] = X[3*i]; sy[i] = X[3*i+1]; sz[i] = X[3*i+2];
        sd[i] = g_d2[b * N_ + i];
    }
    __syncthreads();
    int w = t >> 5, lane = t & 31;
    int q = b * S_ + s0 + w;
    float qx = g_newxyz[3*q], qy = g_newxyz[3*q+1], qz = g_newxyz[3*q+2];
    float q2 = __fadd_rn(__fadd_rn(__fmul_rn(qx,qx), __fmul_rn(qy,qy)), __fmul_rn(qz,qz));
    float key = 3.0e38f; int kid = 0; float curmax = 3.0e38f;
    for (int c = 0; c < N_ / 32; c++) {
        int p = c * 32 + lane;
        float dot = __fadd_rn(__fadd_rn(__fmul_rn(qx, sx[p]),
                                        __fmul_rn(qy, sy[p])),
                              __fmul_rn(qz, sz[p]));
        float d = __fsub_rn(__fadd_rn(q2, sd[p]), __fmul_rn(2.0f, dot));
        unsigned m = __ballot_sync(FULLMASK, d < curmax);
        if (!m) continue;
        if (__popc(m) <= 6) {
            while (m) {
                int src = __ffs(m) - 1;
                m &= m - 1;
                float v  = __shfl_sync(FULLMASK, d, src);
                int   vi = __shfl_sync(FULLMASK, p, src);
                if (v < curmax) {
                    unsigned lt = __ballot_sync(FULLMASK, key < v);
                    int pos = __popc(lt);
                    float ku = __shfl_up_sync(FULLMASK, key, 1);
                    int   iu = __shfl_up_sync(FULLMASK, kid, 1);
                    if (lane == pos)      { key = v;  kid = vi; }
                    else if (lane > pos)  { key = ku; kid = iu; }
                    curmax = __shfl_sync(FULLMASK, key, 31);
                }
            }
        } else {
            float nk = d; int ni = p;
            bitonic_sort_asc(nk, ni, lane);
            float rk = __shfl_sync(FULLMASK, nk, 31 - lane);
            int   ri = __shfl_sync(FULLMASK, ni, 31 - lane);
            if (rk < key) { key = rk; kid = ri; }
            bitonic_merge_asc(key, kid, lane);
            curmax = __shfl_sync(FULLMASK, key, 31);
        }
    }
    g_nn[q * K_ + lane] = kid;
}

// ------------- kernel A: P = W0[:,3:]·points + b0 -------------
__global__ void __launch_bounds__(128, 1) gemmP_kernel(const float* __restrict__ points,
                                                       const float* __restrict__ w,
                                                       const float* __restrict__ bias) {
    extern __shared__ float sh[];
    float* XsT = sh;
    float* Ws  = XsT + 64 * 256;
    int t = threadIdx.x;
    for (int idx = t; idx < 64 * 64; idx += 128) {
        int c = idx >> 6, o = idx & 63;
        Ws[idx] = w[o * 67 + 3 + c];
    }
    #pragma unroll
    for (int rr = 0; rr < 2; rr++) {
        int r = t + rr * 128;
        size_t gr = (size_t)blockIdx.x * 256 + r;
        const float4* src = (const float4*)(points + gr * 64);
        #pragma unroll 4
        for (int ch = 0; ch < 16; ch++) {
            float4 v = src[ch];
            XsT[(ch*4+0)*256 + r] = v.x;
            XsT[(ch*4+1)*256 + r] = v.y;
            XsT[(ch*4+2)*256 + r] = v.z;
            XsT[(ch*4+3)*256 + r] = v.w;
        }
    }
    __syncthreads();
    int rg = t >> 3, cg = t & 7;
    ull acc[8][8];
    #pragma unroll
    for (int i = 0; i < 8; i++) {
        float bb = bias[cg*8+i];
        ull bp = pack2(bb, bb);
        #pragma unroll
        for (int p = 0; p < 8; p++) acc[p][i] = bp;
    }
    for (int c = 0; c < 64; c++) {
        const float4* ap = (const float4*)(XsT + c*256 + rg*16);
        float4 a0 = ap[0], a1 = ap[1], a2 = ap[2], a3 = ap[3];
        ull apair[8] = {pack2(a0.x,a0.y), pack2(a0.z,a0.w),
                        pack2(a1.x,a1.y), pack2(a1.z,a1.w),
                        pack2(a2.x,a2.y), pack2(a2.z,a2.w),
                        pack2(a3.x,a3.y), pack2(a3.z,a3.w)};
        const float4* wp = (const float4*)(Ws + c*64 + cg*8);
        float4 w0 = wp[0], w1 = wp[1];
        float wf[8] = {w0.x,w0.y,w0.z,w0.w,w1.x,w1.y,w1.z,w1.w};
        #pragma unroll
        for (int i = 0; i < 8; i++) {
            ull wd = pack2(wf[i], wf[i]);
            #pragma unroll
            for (int p = 0; p < 8; p++) fma2(acc[p][i], apair[p], wd);
        }
    }
    #pragma unroll
    for (int p = 0; p < 8; p++) {
        float lo[8], hi[8];
        #pragma unroll
        for (int i = 0; i < 8; i++) { float2 v = unpack2(acc[p][i]); lo[i] = v.x; hi[i] = v.y; }
        size_t r0 = (size_t)blockIdx.x * 256 + rg*16 + 2*p;
        float4* d0 = (float4*)(g_P + r0 * 64 + cg*8);
        d0[0] = make_float4(lo[0],lo[1],lo[2],lo[3]);
        d0[1] = make_float4(lo[4],lo[5],lo[6],lo[7]);
        float4* d1 = (float4*)(g_P + (r0+1) * 64 + cg*8);
        d1[0] = make_float4(hi[0],hi[1],hi[2],hi[3]);
        d1[1] = make_float4(hi[4],hi[5],hi[6],hi[7]);
    }
}

// ------------- kernel B: y0 = P[n] + xyz_diff·W0[:,0:3], + BN0 stats -----------
__global__ void __launch_bounds__(256) layer0b_kernel(const float* __restrict__ xyz,
                                                      const float* __restrict__ w) {
    __shared__ float sw[3 * 64];
    __shared__ float Red[2 * 2080];
    int t = threadIdx.x;
    if (t < 192) {
        int k = t >> 6, o = t & 63;
        sw[k * 64 + o] = w[o * 67 + k];
    }
    __syncthreads();
    int rg = t >> 3, cg = t & 7;
    int gr = blockIdx.x * 32 + rg;
    int q = gr >> 5, b = gr >> 15;
    int n = g_nn[gr];
    const float* pp = xyz + ((size_t)b * N_ + n) * 3;
    float dx = __fadd_rn(pp[0], -g_newxyz[3*q]);
    float dy = __fadd_rn(pp[1], -g_newxyz[3*q+1]);
    float dz = __fadd_rn(pp[2], -g_newxyz[3*q+2]);
    const float4* Pp = (const float4*)(g_P + ((size_t)b * N_ + n) * 64) + cg * 2;
    float4 p0 = Pp[0], p1 = Pp[1];
    float y[8] = {p0.x,p0.y,p0.z,p0.w,p1.x,p1.y,p1.z,p1.w};
    #pragma unroll
    for (int i = 0; i < 8; i++) {
        int o = cg*8 + i;
        y[i] = fmaf(dz, sw[128+o], fmaf(dy, sw[64+o], fmaf(dx, sw[o], y[i])));
    }
    float4* dst = (float4*)(g_y0 + (size_t)gr * 64 + cg * 8);
    dst[0] = make_float4(y[0],y[1],y[2],y[3]);
    dst[1] = make_float4(y[4],y[5],y[6],y[7]);
    #pragma unroll
    for (int i = 0; i < 8; i++) Red[rg*65 + cg*8 + i] = y[i];
    __syncthreads();
    if (t < 64) {
        float s = 0.f;
        #pragma unroll 8
        for (int j = 0; j < 32; j++) s += Red[j*65 + t];
        g_part0[(size_t)blockIdx.x*128 + t] = s;
    }
    __syncthreads();
    #pragma unroll
    for (int i = 0; i < 8; i++) Red[rg*65 + cg*8 + i] = y[i]*y[i];
    __syncthreads();
    if (t < 64) {
        float s = 0.f;
        #pragma unroll 8
        for (int j = 0; j < 32; j++) s += Red[j*65 + t];
        g_part0[(size_t)blockIdx.x*128 + 64 + t] = s;
    }
}

// ------------- layer 1: bf16-split mma.sync, BN0+ReLU fused load --------------
// y1[row][c] = BN0relu(y0)[row][0:64] · W1[c][0:64]^T + b1, + BN1 stats partials.
// block: 128 rows x 64 ch, 256 thr (8 warps x 16 rows).
__global__ void __launch_bounds__(256, 1) layer1_mma_kernel(const float* __restrict__ w1,
                                                            const float* __restrict__ b1) {
    extern __shared__ char sm[];
    __nv_bfloat16* Xh = (__nv_bfloat16*)sm;        // [128 rows][72]
    __nv_bfloat16* Xl = Xh + 128 * 72;
    __nv_bfloat16* Wh = Xl + 128 * 72;             // [64 ch][72]
    __nv_bfloat16* Wl = Wh + 64 * 72;
    float* Dst = (float*)sm;                       // reused post-MMA: [128][68]
    __shared__ float sS[64], sH[64], sB[64], sp1[4][64], sp2[4][64];
    int t = threadIdx.x, w = t >> 5, lane = t & 31;
    int g = lane >> 2, tq = lane & 3;

    if (t < 64) { sS[t] = g_scale0[t]; sH[t] = g_shift0[t]; sB[t] = b1[t]; }
    // W1 split: 64 ch x 2 k-halves = 128 items
    if (t < 128) {
        int ch = t & 63, k0 = (t >> 6) * 32;
        const float4* src = (const float4*)(w1 + (size_t)ch * 64 + k0);
        #pragma unroll
        for (int j = 0; j < 8; j++) {
            float4 v = src[j];
            float vv[4] = {v.x, v.y, v.z, v.w};
            #pragma unroll
            for (int i = 0; i < 4; i++) {
                float a = vv[i];
                __nv_bfloat16 h = __float2bfloat16(a);
                __nv_bfloat16 l = __float2bfloat16(__fsub_rn(a, __bfloat162float(h)));
                Wh[ch * 72 + k0 + 4*j + i] = h;
                Wl[ch * 72 + k0 + 4*j + i] = l;
            }
        }
    }
    __syncthreads();   // sS/sH ready
    // X split with BN0+ReLU: row = t&127, k half = (t>>7)*32
    {
        int r = t & 127, k0 = (t >> 7) * 32;
        size_t gr = (size_t)blockIdx.x * 128 + r;
        const float4* src = (const float4*)(g_y0 + gr * 64 + k0);
        #pragma unroll
        for (int j = 0; j < 8; j++) {
            float4 v = src[j];
            float vv[4] = {v.x, v.y, v.z, v.w};
            #pragma unroll
            for (int i = 0; i < 4; i++) {
                int c = k0 + 4*j + i;
                float a = fmaxf(0.f, fmaf(vv[i], sS[c], sH[c]));
                __nv_bfloat16 h = __float2bfloat16(a);
                __nv_bfloat16 l = __float2bfloat16(__fsub_rn(a, __bfloat162float(h)));
                Xh[r * 72 + c] = h;
                Xl[r * 72 + c] = l;
            }
        }
    }
    __syncthreads();

    int R0 = w * 16;
    uint32_t ah[4][4], al[4][4];
    #pragma unroll
    for (int kk = 0; kk < 4; kk++) {
        int kb = kk * 16 + 2 * tq;
        ah[kk][0] = *(const uint32_t*)&Xh[(R0 + g)     * 72 + kb];
        ah[kk][1] = *(const uint32_t*)&Xh[(R0 + g + 8) * 72 + kb];
        ah[kk][2] = *(const uint32_t*)&Xh[(R0 + g)     * 72 + kb + 8];
        ah[kk][3] = *(const uint32_t*)&Xh[(R0 + g + 8) * 72 + kb + 8];
        al[kk][0] = *(const uint32_t*)&Xl[(R0 + g)     * 72 + kb];
        al[kk][1] = *(const uint32_t*)&Xl[(R0 + g + 8) * 72 + kb];
        al[kk][2] = *(const uint32_t*)&Xl[(R0 + g)     * 72 + kb + 8];
        al[kk][3] = *(const uint32_t*)&Xl[(R0 + g + 8) * 72 + kb + 8];
    }

    float c[8][4];
    #pragma unroll
    for (int cg = 0; cg < 8; cg++)
        #pragma unroll
        for (int i = 0; i < 4; i++) c[cg][i] = 0.f;

    #pragma unroll
    for (int cg = 0; cg < 8; cg++) {
        int chb = cg * 8 + g;
        #pragma unroll
        for (int kk = 0; kk < 4; kk++) {
            int kb = kk * 16 + 2 * tq;
            uint32_t bh0 = *(const uint32_t*)&Wh[chb * 72 + kb];
            uint32_t bh1 = *(const uint32_t*)&Wh[chb * 72 + kb + 8];
            uint32_t bl0 = *(const uint32_t*)&Wl[chb * 72 + kb];
            uint32_t bl1 = *(const uint32_t*)&Wl[chb * 72 + kb + 8];
            mma16816(c[cg], ah[kk], bh0, bh1);
            mma16816(c[cg], ah[kk], bl0, bl1);
            mma16816(c[cg], al[kk], bh0, bh1);
        }
    }
    __syncthreads();   // tiles done; reuse smem for D staging

    #pragma unroll
    for (int cg = 0; cg < 8; cg++) {
        int c0i = cg * 8 + 2 * tq;
        int r0 = R0 + g, r1 = r0 + 8;
        *(float2*)&Dst[r0 * 68 + c0i] = make_float2(c[cg][0], c[cg][1]);
        *(float2*)&Dst[r1 * 68 + c0i] = make_float2(c[cg][2], c[cg][3]);
    }
    __syncthreads();

    // epilogue: +bias, write y1 (coalesced 256B runs), stats partials
    {
        int col = t & 63, grp = t >> 6;       // 4 groups x 32 rows
        float bb = sB[col];
        float s1 = 0.f, s2 = 0.f;
        int rb = grp * 32;
        size_t gbase = (size_t)blockIdx.x * 128 + rb;
        #pragma unroll 8
        for (int r = 0; r < 32; r++) {
            float v = Dst[(rb + r) * 68 + col] + bb;
            g_y1[(gbase + r) * 64 + col] = v;
            s1 += v;
            s2 = fmaf(v, v, s2);
        }
        sp1[grp][col] = s1;
        sp2[grp][col] = s2;
    }
    __syncthreads();
    if (t < 64) {
        g_part1[(size_t)blockIdx.x * 128 + t] = sp1[0][t] + sp1[1][t] + sp1[2][t] + sp1[3][t];
    } else if (t < 128) {
        int col = t - 64;
        g_part1[(size_t)blockIdx.x * 128 + 64 + col] = sp2[0][col] + sp2[1][col] + sp2[2][col] + sp2[3][col];
    }
}

// ------------- layer 2: bf16-split mma.sync, fused pool -----------------------
__global__ void __launch_bounds__(256, 1) layer2_mma_kernel(const float* __restrict__ w2,
                                                            const float* __restrict__ b2) {
    extern __shared__ char sm[];
    __nv_bfloat16* Xh = (__nv_bfloat16*)sm;        // [128 rows][72]
    __nv_bfloat16* Xl = Xh + 128 * 72;
    __nv_bfloat16* Wh = Xl + 128 * 72;             // [128 ch][72]
    __nv_bfloat16* Wl = Wh + 128 * 72;
    float* Dst = (float*)sm;                       // reused post-MMA: [128][132]
    __shared__ float sS[64], sH[64], sB[128], sr1[128], sr2[128];
    int t = threadIdx.x, w = t >> 5, lane = t & 31;
    int g = lane >> 2, tq = lane & 3;

    if (t < 64) { sS[t] = g_scale1[t]; sH[t] = g_shift1[t]; }
    if (t < 128) sB[t] = b2[t];
    {
        int ch = t & 127, k0 = (t >> 7) * 32;
        const float4* src = (const float4*)(w2 + (size_t)ch * 64 + k0);
        #pragma unroll
        for (int j = 0; j < 8; j++) {
            float4 v = src[j];
            float vv[4] = {v.x, v.y, v.z, v.w};
            #pragma unroll
            for (int i = 0; i < 4; i++) {
                float a = vv[i];
                __nv_bfloat16 h = __float2bfloat16(a);
                __nv_bfloat16 l = __float2bfloat16(__fsub_rn(a, __bfloat162float(h)));
                Wh[ch * 72 + k0 + 4*j + i] = h;
                Wl[ch * 72 + k0 + 4*j + i] = l;
            }
        }
    }
    __syncthreads();
    {
        int r = t & 127, k0 = (t >> 7) * 32;
        size_t gr = (size_t)blockIdx.x * 128 + r;
        const float4* src = (const float4*)(g_y1 + gr * 64 + k0);
        #pragma unroll
        for (int j = 0; j < 8; j++) {
            float4 v = src[j];
            float vv[4] = {v.x, v.y, v.z, v.w};
            #pragma unroll
            for (int i = 0; i < 4; i++) {
                int c = k0 + 4*j + i;
                float a = fmaxf(0.f, fmaf(vv[i], sS[c], sH[c]));
                __nv_bfloat16 h = __float2bfloat16(a);
                __nv_bfloat16 l = __float2bfloat16(__fsub_rn(a, __bfloat162float(h)));
                Xh[r * 72 + c] = h;
                Xl[r * 72 + c] = l;
            }
        }
    }
    __syncthreads();

    int R0 = w * 16;
    uint32_t ah[4][4], al[4][4];
    #pragma unroll
    for (int kk = 0; kk < 4; kk++) {
        int kb = kk * 16 + 2 * tq;
        ah[kk][0] = *(const uint32_t*)&Xh[(R0 + g)     * 72 + kb];
        ah[kk][1] = *(const uint32_t*)&Xh[(R0 + g + 8) * 72 + kb];
        ah[kk][2] = *(const uint32_t*)&Xh[(R0 + g)     * 72 + kb + 8];
        ah[kk][3] = *(const uint32_t*)&Xh[(R0 + g + 8) * 72 + kb + 8];
        al[kk][0] = *(const uint32_t*)&Xl[(R0 + g)     * 72 + kb];
        al[kk][1] = *(const uint32_t*)&Xl[(R0 + g + 8) * 72 + kb];
        al[kk][2] = *(const uint32_t*)&Xl[(R0 + g)     * 72 + kb + 8];
        al[kk][3] = *(const uint32_t*)&Xl[(R0 + g + 8) * 72 + kb + 8];
    }

    float c[16][4];
    #pragma unroll
    for (int cg = 0; cg < 16; cg++)
        #pragma unroll
        for (int i = 0; i < 4; i++) c[cg][i] = 0.f;

    #pragma unroll
    for (int cg = 0; cg < 16; cg++) {
        int chb = cg * 8 + g;
        #pragma unroll
        for (int kk = 0; kk < 4; kk++) {
            int kb = kk * 16 + 2 * tq;
            uint32_t bh0 = *(const uint32_t*)&Wh[chb * 72 + kb];
            uint32_t bh1 = *(const uint32_t*)&Wh[chb * 72 + kb + 8];
            uint32_t bl0 = *(const uint32_t*)&Wl[chb * 72 + kb];
            uint32_t bl1 = *(const uint32_t*)&Wl[chb * 72 + kb + 8];
            mma16816(c[cg], ah[kk], bh0, bh1);
            mma16816(c[cg], ah[kk], bl0, bl1);
            mma16816(c[cg], al[kk], bh0, bh1);
        }
    }
    __syncthreads();

    #pragma unroll
    for (int cg = 0; cg < 16; cg++) {
        int c0i = cg * 8 + 2 * tq;
        int r0 = R0 + g, r1 = r0 + 8;
        *(float2*)&Dst[r0 * 132 + c0i] = make_float2(c[cg][0], c[cg][1]);
        *(float2*)&Dst[r1 * 132 + c0i] = make_float2(c[cg][2], c[cg][3]);
    }
    __syncthreads();

    {
        int col = t & 127, half = t >> 7;
        float bb = sB[col];
        float s1 = 0.f, s2 = 0.f;
        #pragma unroll
        for (int grp = 0; grp < 2; grp++) {
            int rb = half * 64 + grp * 32;
            float mx = -3.4e38f, mn = 3.4e38f;
            #pragma unroll 8
            for (int r = 0; r < 32; r++) {
                float v = Dst[(rb + r) * 132 + col] + bb;
                s1 += v;
                s2 = fmaf(v, v, s2);
                mx = fmaxf(mx, v);
                mn = fminf(mn, v);
            }
            size_t bs = (size_t)blockIdx.x * 4 + half * 2 + grp;
            g_pmax[bs * 128 + col] = mx;
            g_pmin[bs * 128 + col] = mn;
        }
        if (half == 0) { sr1[col] = s1; sr2[col] = s2; }
        __syncthreads();
        if (half == 1) {
            g_part2[(size_t)blockIdx.x * 256 + col]       = sr1[col] + s1;
            g_part2[(size_t)blockIdx.x * 256 + 128 + col] = sr2[col] + s2;
        }
    }
}

// ------------- BN stats -------------
__global__ void __launch_bounds__(256) stats_kernel(int layer, int nblk, int C,
                             const float* __restrict__ gamma, const float* __restrict__ beta) {
    int c = blockIdx.x;
    int t = threadIdx.x;
    const float* part = (layer == 0) ? g_part0 : (layer == 1) ? g_part1 : g_part2;
    float s1 = 0.f, s2 = 0.f;
    for (int bk = t; bk < nblk; bk += 256) {
        s1 += part[(size_t)bk*2*C + c];
        s2 += part[(size_t)bk*2*C + C + c];
    }
    __shared__ float r1[256], r2[256];
    r1[t] = s1; r2[t] = s2;
    __syncthreads();
    for (int off = 128; off >= 1; off >>= 1) {
        if (t < off) { r1[t] += r1[t+off]; r2[t] += r2[t+off]; }
        __syncthreads();
    }
    if (t == 0) {
        const float n = 524288.f;
        float mean = r1[0] / n;
        float var = r2[0] / n - mean * mean;
        float sc = gamma[c] * rsqrtf(var + EPSF);
        float sf = beta[c] - mean * sc;
        if (layer == 0)      { g_scale0[c] = sc; g_shift0[c] = sf; }
        else if (layer == 1) { g_scale1[c] = sc; g_shift1[c] = sf; }
        else                 { g_scale2[c] = sc; g_shift2[c] = sf; }
    }
}

// ------------- pool epilogue -------------
__global__ void pool2_kernel(float* __restrict__ out, int pts_off) {
    int bs = blockIdx.x;
    int c = threadIdx.x;
    float sc = g_scale2[c], sf = g_shift2[c];
    float v = (sc >= 0.f) ? g_pmax[(size_t)bs*128 + c] : g_pmin[(size_t)bs*128 + c];
    float m = fmaxf(fmaf(v, sc, sf), 0.f);
    out[pts_off + (bs >> 10) * (128 * 1024) + c * 1024 + (bs & 1023)] = m;
}

extern "C" void kernel_launch(void* const* d_in, const int* in_sizes, int n_in,
                              void* d_out, int out_size) {
    const float* xyz    = (const float*)d_in[0];
    const float* points = (const float*)d_in[1];
    const float* w0 = (const float*)d_in[2];  const float* b0  = (const float*)d_in[3];
    const float* g0 = (const float*)d_in[4];  const float* be0 = (const float*)d_in[5];
    const float* w1 = (const float*)d_in[6];  const float* b1  = (const float*)d_in[7];
    const float* g1 = (const float*)d_in[8];  const float* be1 = (const float*)d_in[9];
    const float* w2 = (const float*)d_in[10]; const float* b2  = (const float*)d_in[11];
    const float* g2 = (const float*)d_in[12]; const float* be2 = (const float*)d_in[13];
    float* out = (float*)d_out;

    int npts = B_ * 128 * S_;
    int pts_off = out_size - npts;
    if (pts_off < 0) pts_off = 0;

    cudaFuncSetAttribute(fps_kernel,       cudaFuncAttributeMaxDynamicSharedMemorySize, FPS_SMEM);
    cudaFuncSetAttribute(knn_kernel,       cudaFuncAttributeMaxDynamicSharedMemorySize, KNN_SMEM);
    cudaFuncSetAttribute(gemmP_kernel,     cudaFuncAttributeMaxDynamicSharedMemorySize, LA_SMEM);
    cudaFuncSetAttribute(layer1_mma_kernel,cudaFuncAttributeMaxDynamicSharedMemorySize, L1M_SMEM);
    cudaFuncSetAttribute(layer2_mma_kernel,cudaFuncAttributeMaxDynamicSharedMemorySize, L2M_SMEM);

    fps_kernel<<<B_, 1024, FPS_SMEM>>>(xyz, out, pts_off > 0 ? 1 : 0);
    gemmP_kernel<<<256, 128, LA_SMEM>>>(points, w0, b0);
    knn_kernel<<<B_ * 128, 256, KNN_SMEM>>>(xyz);
    layer0b_kernel<<<16384, 256>>>(xyz, w0);
    stats_kernel<<<64, 256>>>(0, 16384, 64, g0, be0);
    layer1_mma_kernel<<<4096, 256, L1M_SMEM>>>(w1, b1);
    stats_kernel<<<64, 256>>>(1, 4096, 64, g1, be1);
    layer2_mma_kernel<<<4096, 256, L2M_SMEM>>>(w2, b2);
    stats_kernel<<<128, 256>>>(2, 4096, 128, g2, be2);
    pool2_kernel<<<B_ * S_, 128>>>(out, pts_off);
}